// round 5
// baseline (speedup 1.0000x reference)
#include <cuda_runtime.h>
#include <math.h>
#include <stdint.h>

#define B   2
#define T   1024
#define H   2048
#define NH  32
#define NKV 8
#define HD  64
#define IM  8192
#define M   (B*T)

// ---------------- scratch (device globals; no allocation) ----------------
__device__ __align__(16) float g_xn  [M * H];
__device__ __align__(16) float g_q   [M * NH * HD];
__device__ __align__(16) float g_k   [M * NKV * HD];
__device__ __align__(16) float g_v   [M * NKV * HD];
__device__ __align__(16) float g_attn[M * NH * HD];
__device__ __align__(16) float g_h2  [M * H];
__device__ __align__(16) float g_xn2 [M * H];
__device__ __align__(16) float g_g   [(size_t)M * IM];
__device__ __align__(16) float g_u   [(size_t)M * IM];

// ---------------- helpers ----------------
__device__ __forceinline__ uint32_t smem_u32(const void* p) {
    uint32_t a;
    asm("{ .reg .u64 t; cvta.to.shared.u64 t, %1; cvt.u32.u64 %0, t; }"
        : "=r"(a) : "l"(p));
    return a;
}

__device__ __forceinline__ void cp_async16(uint32_t dst, const void* src) {
    asm volatile("cp.async.cg.shared.global [%0], [%1], 16;"
                 :: "r"(dst), "l"(src));
}
#define CP_ASYNC_COMMIT() asm volatile("cp.async.commit_group;" ::: "memory")
#define CP_ASYNC_WAIT0()  asm volatile("cp.async.wait_group 0;" ::: "memory")

__device__ __forceinline__ void mma_tf32(float& c0, float& c1, float& c2, float& c3,
                                         uint32_t a0, uint32_t a1, uint32_t a2, uint32_t a3,
                                         uint32_t b0, uint32_t b1) {
    asm volatile(
        "mma.sync.aligned.m16n8k8.row.col.f32.tf32.tf32.f32 "
        "{%0,%1,%2,%3}, {%4,%5,%6,%7}, {%8,%9}, {%0,%1,%2,%3};"
        : "+f"(c0), "+f"(c1), "+f"(c2), "+f"(c3)
        : "r"(a0), "r"(a1), "r"(a2), "r"(a3), "r"(b0), "r"(b1));
}

__device__ __forceinline__ uint32_t tf32_rna(float x) {
    uint32_t r;
    asm("cvt.rna.tf32.f32 %0, %1;" : "=r"(r) : "f"(x));
    return r;
}

// ---------------- 3xTF32 GEMM core (512 threads, CTA tile 128x128) --------
// C[m,n] = sum_k A[m,k]*Bm[n,k] (+res). K % 32 == 0.
#define GPAD 36
#define A_BUF_FLOATS (128 * GPAD)                 // 4608 floats
#define GEMM_DSMEM   (4 * A_BUF_FLOATS * 4)       // 73728 B

__device__ __forceinline__ void gemm_tile(float* sm,
                                          const float* __restrict__ A,
                                          const float* __restrict__ Bm,
                                          const float* __restrict__ res,
                                          float* __restrict__ C,
                                          int N, int K, int bm, int bn) {
    float* As[2] = { sm,                 sm + 2 * A_BUF_FLOATS };
    float* Bs[2] = { sm + A_BUF_FLOATS,  sm + 3 * A_BUF_FLOATS };
    const uint32_t smem_base = smem_u32(sm);

    const int tid  = threadIdx.x;
    const int wid  = tid >> 5;
    const int lane = tid & 31;
    const int wm   = wid >> 2;           // 0..3 -> 32-row band
    const int wn   = wid & 3;            // 0..3 -> 32-col band
    const int gid  = lane >> 2;          // 0..7
    const int tig  = lane & 3;           // 0..3
    const int KC   = K >> 5;
    const int lrow = tid >> 3;           // 0..63
    const int lc4  = tid & 7;            // 0..7

    float acc[2][4][4];
    #pragma unroll
    for (int i = 0; i < 2; i++)
        #pragma unroll
        for (int j = 0; j < 4; j++)
            #pragma unroll
            for (int l = 0; l < 4; l++) acc[i][j][l] = 0.f;

    auto issue_load = [&](int c, int buf) {
        const int k0 = c << 5;
        uint32_t abase = smem_base + (buf ? 2 * A_BUF_FLOATS * 4 : 0);
        uint32_t bbase = abase + A_BUF_FLOATS * 4;
        #pragma unroll
        for (int it = 0; it < 2; it++) {
            int row = it * 64 + lrow;
            cp_async16(abase + (row * GPAD + lc4 * 4) * 4,
                       A + (size_t)(bm + row) * K + k0 + lc4 * 4);
            cp_async16(bbase + (row * GPAD + lc4 * 4) * 4,
                       Bm + (size_t)(bn + row) * K + k0 + lc4 * 4);
        }
        CP_ASYNC_COMMIT();
    };

    issue_load(0, 0);

    for (int c = 0; c < KC; c++) {
        const int buf = c & 1;
        CP_ASYNC_WAIT0();
        __syncthreads();
        if (c + 1 < KC) issue_load(c + 1, buf ^ 1);

        const float* a_s = As[buf];
        const float* b_s = Bs[buf];

        #pragma unroll
        for (int ks = 0; ks < 4; ks++) {
            const int k0 = ks * 8;
            uint32_t ah[2][4], al[2][4];
            #pragma unroll
            for (int mt = 0; mt < 2; mt++) {
                int r0 = wm * 32 + mt * 16 + gid;
                float x0 = a_s[r0 * GPAD + k0 + tig];
                float x1 = a_s[(r0 + 8) * GPAD + k0 + tig];
                float x2 = a_s[r0 * GPAD + k0 + tig + 4];
                float x3 = a_s[(r0 + 8) * GPAD + k0 + tig + 4];
                ah[mt][0] = tf32_rna(x0); al[mt][0] = tf32_rna(x0 - __uint_as_float(ah[mt][0]));
                ah[mt][1] = tf32_rna(x1); al[mt][1] = tf32_rna(x1 - __uint_as_float(ah[mt][1]));
                ah[mt][2] = tf32_rna(x2); al[mt][2] = tf32_rna(x2 - __uint_as_float(ah[mt][2]));
                ah[mt][3] = tf32_rna(x3); al[mt][3] = tf32_rna(x3 - __uint_as_float(ah[mt][3]));
            }
            uint32_t bh[4][2], bl[4][2];
            #pragma unroll
            for (int nt = 0; nt < 4; nt++) {
                int nr = wn * 32 + nt * 8 + gid;
                float y0 = b_s[nr * GPAD + k0 + tig];
                float y1 = b_s[nr * GPAD + k0 + tig + 4];
                bh[nt][0] = tf32_rna(y0); bl[nt][0] = tf32_rna(y0 - __uint_as_float(bh[nt][0]));
                bh[nt][1] = tf32_rna(y1); bl[nt][1] = tf32_rna(y1 - __uint_as_float(bh[nt][1]));
            }
            #pragma unroll
            for (int mt = 0; mt < 2; mt++)
                #pragma unroll
                for (int nt = 0; nt < 4; nt++) {
                    mma_tf32(acc[mt][nt][0], acc[mt][nt][1],
                             acc[mt][nt][2], acc[mt][nt][3],
                             ah[mt][0], ah[mt][1], ah[mt][2], ah[mt][3],
                             bl[nt][0], bl[nt][1]);
                    mma_tf32(acc[mt][nt][0], acc[mt][nt][1],
                             acc[mt][nt][2], acc[mt][nt][3],
                             al[mt][0], al[mt][1], al[mt][2], al[mt][3],
                             bh[nt][0], bh[nt][1]);
                    mma_tf32(acc[mt][nt][0], acc[mt][nt][1],
                             acc[mt][nt][2], acc[mt][nt][3],
                             ah[mt][0], ah[mt][1], ah[mt][2], ah[mt][3],
                             bh[nt][0], bh[nt][1]);
                }
        }
        __syncthreads();
    }

    #pragma unroll
    for (int mt = 0; mt < 2; mt++) {
        int r0 = bm + wm * 32 + mt * 16 + gid;
        #pragma unroll
        for (int nt = 0; nt < 4; nt++) {
            int col = bn + wn * 32 + nt * 8 + tig * 2;
            size_t o0 = (size_t)r0 * N + col;
            size_t o1 = (size_t)(r0 + 8) * N + col;
            float2 v0 = make_float2(acc[mt][nt][0], acc[mt][nt][1]);
            float2 v1 = make_float2(acc[mt][nt][2], acc[mt][nt][3]);
            if (res) {
                float2 r0v = *(const float2*)(res + o0);
                float2 r1v = *(const float2*)(res + o1);
                v0.x += r0v.x; v0.y += r0v.y;
                v1.x += r1v.x; v1.y += r1v.y;
            }
            *(float2*)(C + o0) = v0;
            *(float2*)(C + o1) = v1;
        }
    }
}

// ---- generic GEMM (o-proj, down-proj) ----
__global__ void __launch_bounds__(512, 1)
gemm_mma_kernel(const float* __restrict__ A, const float* __restrict__ Bm,
                const float* __restrict__ res, float* __restrict__ C,
                int N, int K) {
    extern __shared__ float sm[];
    gemm_tile(sm, A, Bm, res, C, N, K, blockIdx.y * 128, blockIdx.x * 128);
}

// ---- fused QKV projection: blockIdx.x 0..15 Q, 16..19 K, 20..23 V ----
__global__ void __launch_bounds__(512, 1)
gemm_qkv_kernel(const float* __restrict__ A,
                const float* __restrict__ wq, const float* __restrict__ wk,
                const float* __restrict__ wv,
                float* __restrict__ q, float* __restrict__ k, float* __restrict__ v) {
    extern __shared__ float sm[];
    const int ct = blockIdx.x;
    const float* Bm; float* C; int N, bn;
    if (ct < 16)      { Bm = wq; C = q; N = NH  * HD; bn = ct * 128; }
    else if (ct < 20) { Bm = wk; C = k; N = NKV * HD; bn = (ct - 16) * 128; }
    else              { Bm = wv; C = v; N = NKV * HD; bn = (ct - 20) * 128; }
    gemm_tile(sm, A, Bm, nullptr, C, N, H, blockIdx.y * 128, bn);
}

// ---- fused gate/up: blockIdx.x 0..63 gate, 64..127 up ----
__global__ void __launch_bounds__(512, 1)
gemm_gu_kernel(const float* __restrict__ A,
               const float* __restrict__ wg, const float* __restrict__ wu,
               float* __restrict__ gg, float* __restrict__ uu) {
    extern __shared__ float sm[];
    const int ct = blockIdx.x;
    const float* Bm = (ct < 64) ? wg : wu;
    float* C        = (ct < 64) ? gg : uu;
    const int bn    = (ct & 63) * 128;
    gemm_tile(sm, A, Bm, nullptr, C, IM, H, blockIdx.y * 128, bn);
}

// ---------------- RMSNorm ----------------
__global__ void rmsnorm_kernel(const float* __restrict__ x,
                               const float* __restrict__ w,
                               float* __restrict__ out) {
    int row = blockIdx.x;
    const float* xr = x + (size_t)row * H;
    float ss = 0.f;
    for (int i = threadIdx.x; i < H / 4; i += blockDim.x) {
        float4 v = ((const float4*)xr)[i];
        ss += v.x * v.x + v.y * v.y + v.z * v.z + v.w * v.w;
    }
    __shared__ float red[32];
    #pragma unroll
    for (int o = 16; o; o >>= 1) ss += __shfl_xor_sync(0xffffffffu, ss, o);
    if ((threadIdx.x & 31) == 0) red[threadIdx.x >> 5] = ss;
    __syncthreads();
    if (threadIdx.x < 32) {
        float v = (threadIdx.x < (blockDim.x >> 5)) ? red[threadIdx.x] : 0.f;
        #pragma unroll
        for (int o = 16; o; o >>= 1) v += __shfl_xor_sync(0xffffffffu, v, o);
        if (threadIdx.x == 0) red[0] = v;
    }
    __syncthreads();
    float r = rsqrtf(red[0] / (float)H + 1e-6f);
    float* orow = out + (size_t)row * H;
    for (int i = threadIdx.x; i < H / 4; i += blockDim.x) {
        float4 v = ((const float4*)xr)[i];
        float4 wv = ((const float4*)w)[i];
        float4 o4 = make_float4(v.x * r * wv.x, v.y * r * wv.y,
                                v.z * r * wv.z, v.w * r * wv.w);
        ((float4*)orow)[i] = o4;
    }
}

// ---------------- RoPE ----------------
__global__ void rope_q_kernel(float* __restrict__ q,
                              const float* __restrict__ cosp,
                              const float* __restrict__ sinp,
                              const int* __restrict__ pos) {
    int idx = blockIdx.x * blockDim.x + threadIdx.x;
    int d2 = idx & 31;
    int h  = (idx >> 5) & (NH - 1);
    int bt = idx >> 10;
    int p  = pos[bt];
    float c = cosp[p * 32 + d2], s = sinp[p * 32 + d2];
    size_t base = (size_t)bt * (NH * HD) + h * HD + 2 * d2;
    float x1 = q[base], x2 = q[base + 1];
    q[base]     = x1 * c - x2 * s;
    q[base + 1] = x1 * s + x2 * c;
}

__global__ void rope_kv_kernel(float* __restrict__ k, const float* __restrict__ v,
                               const float* __restrict__ cosp,
                               const float* __restrict__ sinp,
                               const int* __restrict__ pos,
                               float* __restrict__ outk, float* __restrict__ outv) {
    int idx = blockIdx.x * blockDim.x + threadIdx.x;
    int d2 = idx & 31;
    int h  = (idx >> 5) & (NKV - 1);
    int bt = idx >> 8;
    int t  = bt & (T - 1);
    int b  = bt >> 10;
    int p  = pos[bt];
    float c = cosp[p * 32 + d2], s = sinp[p * 32 + d2];
    size_t base = (size_t)bt * (NKV * HD) + h * HD + 2 * d2;
    float x1 = k[base], x2 = k[base + 1];
    float r1 = x1 * c - x2 * s;
    float r2 = x1 * s + x2 * c;
    k[base] = r1; k[base + 1] = r2;
    size_t ob = (((size_t)(b * NKV + h)) * T + t) * HD + 2 * d2;
    outk[ob] = r1;       outk[ob + 1] = r2;
    outv[ob] = v[base];  outv[ob + 1] = v[base + 1];
}

// ---------------- Flash attention (64x64 tiles, fp32) ----------------
__global__ void __launch_bounds__(256)
attn_kernel(const float* __restrict__ Q, const float* __restrict__ Kg,
            const float* __restrict__ Vg, float* __restrict__ O) {
    __shared__ __align__(16) float QsT[64][64];
    __shared__ __align__(16) float KsT[64][64];
    __shared__ __align__(16) float Vs [64][64];
    float (*Ps)[64] = KsT;

    const int qt = blockIdx.x, h = blockIdx.y, b = blockIdx.z;
    const int kvh = h >> 2;
    const int tid = threadIdx.x;
    const int rg = tid >> 4, cg = tid & 15;
    const int m0 = rg * 4, n0 = cg * 4;

    {
        const int m = tid >> 2;
        const int d0 = (tid & 3) * 16;
        const float* qp = Q + ((size_t)(b * T + qt * 64 + m)) * (NH * HD) + h * HD + d0;
        #pragma unroll
        for (int i = 0; i < 16; i++) QsT[d0 + i][m] = qp[i];
    }

    float o_acc[4][4] = {};
    float row_max[4] = {-1e30f, -1e30f, -1e30f, -1e30f};
    float row_sum[4] = {0.f, 0.f, 0.f, 0.f};

    for (int kt = 0; kt <= qt; kt++) {
        __syncthreads();
        {
            const int n = tid >> 2;
            const int d0 = (tid & 3) * 16;
            const float* kp = Kg + ((size_t)(b * T + kt * 64 + n)) * (NKV * HD) + kvh * HD + d0;
            const float* vp = Vg + ((size_t)(b * T + kt * 64 + n)) * (NKV * HD) + kvh * HD + d0;
            #pragma unroll
            for (int i = 0; i < 16; i++) KsT[d0 + i][n] = kp[i];
            #pragma unroll
            for (int i = 0; i < 16; i += 4)
                *(float4*)&Vs[n][d0 + i] = *(const float4*)(vp + i);
        }
        __syncthreads();

        float s[4][4] = {};
        #pragma unroll 16
        for (int d = 0; d < 64; d++) {
            float4 av = *(const float4*)&QsT[d][m0];
            float4 bv = *(const float4*)&KsT[d][n0];
            float aa[4] = {av.x, av.y, av.z, av.w};
            float bb[4] = {bv.x, bv.y, bv.z, bv.w};
            #pragma unroll
            for (int i = 0; i < 4; i++)
                #pragma unroll
                for (int j = 0; j < 4; j++)
                    s[i][j] = fmaf(aa[i], bb[j], s[i][j]);
        }

        const float scale = 0.125f;
        if (kt == qt) {
            #pragma unroll
            for (int i = 0; i < 4; i++)
                #pragma unroll
                for (int j = 0; j < 4; j++)
                    s[i][j] = (n0 + j <= m0 + i) ? s[i][j] * scale : -1e30f;
        } else {
            #pragma unroll
            for (int i = 0; i < 4; i++)
                #pragma unroll
                for (int j = 0; j < 4; j++)
                    s[i][j] *= scale;
        }

        float p[4][4];
        #pragma unroll
        for (int i = 0; i < 4; i++) {
            float mx = fmaxf(fmaxf(s[i][0], s[i][1]), fmaxf(s[i][2], s[i][3]));
            #pragma unroll
            for (int o = 1; o < 16; o <<= 1)
                mx = fmaxf(mx, __shfl_xor_sync(0xffffffffu, mx, o));
            float nm = fmaxf(row_max[i], mx);
            float alpha = __expf(row_max[i] - nm);
            row_max[i] = nm;
            float rs = 0.f;
            #pragma unroll
            for (int j = 0; j < 4; j++) { p[i][j] = __expf(s[i][j] - nm); rs += p[i][j]; }
            #pragma unroll
            for (int o = 1; o < 16; o <<= 1)
                rs += __shfl_xor_sync(0xffffffffu, rs, o);
            row_sum[i] = row_sum[i] * alpha + rs;
            #pragma unroll
            for (int j = 0; j < 4; j++) o_acc[i][j] *= alpha;
        }

        __syncthreads();
        #pragma unroll
        for (int i = 0; i < 4; i++)
            #pragma unroll
            for (int j = 0; j < 4; j++)
                Ps[m0 + i][n0 + j] = p[i][j];
        __syncthreads();

        #pragma unroll 8
        for (int n = 0; n < 64; n++) {
            float4 vv = *(const float4*)&Vs[n][n0];
            float vb[4] = {vv.x, vv.y, vv.z, vv.w};
            #pragma unroll
            for (int i = 0; i < 4; i++) {
                float pv = Ps[m0 + i][n];
                #pragma unroll
                for (int j = 0; j < 4; j++)
                    o_acc[i][j] = fmaf(pv, vb[j], o_acc[i][j]);
            }
        }
    }

    #pragma unroll
    for (int i = 0; i < 4; i++) {
        float inv = 1.f / row_sum[i];
        int t = qt * 64 + m0 + i;
        float4 ov = make_float4(o_acc[i][0] * inv, o_acc[i][1] * inv,
                                o_acc[i][2] * inv, o_acc[i][3] * inv);
        *(float4*)(O + ((size_t)(b * T + t)) * (NH * HD) + h * HD + n0) = ov;
    }
}

// ---------------- SwiGLU elementwise ----------------
__global__ void silu_mul_kernel(float* __restrict__ g, const float* __restrict__ u) {
    int i = blockIdx.x * blockDim.x + threadIdx.x;
    float4 gv = ((const float4*)g)[i];
    float4 uv = ((const float4*)u)[i];
    gv.x = gv.x / (1.f + __expf(-gv.x)) * uv.x;
    gv.y = gv.y / (1.f + __expf(-gv.y)) * uv.y;
    gv.z = gv.z / (1.f + __expf(-gv.z)) * uv.z;
    gv.w = gv.w / (1.f + __expf(-gv.w)) * uv.w;
    ((float4*)g)[i] = gv;
}

// ---------------- launch ----------------
extern "C" void kernel_launch(void* const* d_in, const int* in_sizes, int n_in,
                              void* d_out, int out_size) {
    const float* hs   = (const float*)d_in[0];
    const float* cosp = (const float*)d_in[1];
    const float* sinp = (const float*)d_in[2];
    const int*   pos  = (const int*)  d_in[3];
    const float* n1w  = (const float*)d_in[5];
    const float* wq   = (const float*)d_in[6];
    const float* wk   = (const float*)d_in[7];
    const float* wv   = (const float*)d_in[8];
    const float* wo   = (const float*)d_in[9];
    const float* n2w  = (const float*)d_in[10];
    const float* wg   = (const float*)d_in[11];
    const float* wu   = (const float*)d_in[12];
    const float* wd   = (const float*)d_in[13];

    float *xn, *q, *k, *v, *attn, *h2, *xn2, *gg, *uu;
    cudaGetSymbolAddress((void**)&xn,   g_xn);
    cudaGetSymbolAddress((void**)&q,    g_q);
    cudaGetSymbolAddress((void**)&k,    g_k);
    cudaGetSymbolAddress((void**)&v,    g_v);
    cudaGetSymbolAddress((void**)&attn, g_attn);
    cudaGetSymbolAddress((void**)&h2,   g_h2);
    cudaGetSymbolAddress((void**)&xn2,  g_xn2);
    cudaGetSymbolAddress((void**)&gg,   g_g);
    cudaGetSymbolAddress((void**)&uu,   g_u);

    float* out_x = (float*)d_out;
    float* out_k = out_x + (size_t)M * H;
    float* out_v = out_k + (size_t)B * NKV * T * HD;

    cudaFuncSetAttribute(gemm_mma_kernel,
                         cudaFuncAttributeMaxDynamicSharedMemorySize, GEMM_DSMEM);
    cudaFuncSetAttribute(gemm_qkv_kernel,
                         cudaFuncAttributeMaxDynamicSharedMemorySize, GEMM_DSMEM);
    cudaFuncSetAttribute(gemm_gu_kernel,
                         cudaFuncAttributeMaxDynamicSharedMemorySize, GEMM_DSMEM);

    // 1. RMSNorm 1
    rmsnorm_kernel<<<M, 256>>>(hs, n1w, xn);
    // 2. fused Q/K/V projections
    gemm_qkv_kernel<<<dim3(24, M / 128), 512, GEMM_DSMEM>>>(xn, wq, wk, wv, q, k, v);
    // 3. RoPE + KV-cache writeout
    rope_q_kernel <<<(B * T * NH  * (HD / 2)) / 256, 256>>>(q, cosp, sinp, pos);
    rope_kv_kernel<<<(B * T * NKV * (HD / 2)) / 256, 256>>>(k, v, cosp, sinp, pos,
                                                            out_k, out_v);
    // 4. Attention
    attn_kernel<<<dim3(T / 64, NH, B), 256>>>(q, k, v, attn);
    // 5. O-projection + residual
    gemm_mma_kernel<<<dim3(H / 128, M / 128), 512, GEMM_DSMEM>>>(attn, wo, hs, h2, H, NH * HD);
    // 6. RMSNorm 2
    rmsnorm_kernel<<<M, 256>>>(h2, n2w, xn2);
    // 7. fused MLP gate/up
    gemm_gu_kernel<<<dim3(128, M / 128), 512, GEMM_DSMEM>>>(xn2, wg, wu, gg, uu);
    // 8. SwiGLU
    silu_mul_kernel<<<((size_t)M * IM / 4) / 256, 256>>>(gg, uu);
    // 9. Down projection + residual -> x output
    gemm_mma_kernel<<<dim3(H / 128, M / 128), 512, GEMM_DSMEM>>>(gg, wd, h2, out_x, H, IM);
}

// round 6
// speedup vs baseline: 1.1266x; 1.1266x over previous
#include <cuda_runtime.h>
#include <math.h>
#include <stdint.h>

#define B   2
#define T   1024
#define H   2048
#define NH  32
#define NKV 8
#define HD  64
#define IM  8192
#define M   (B*T)

// ---------------- scratch (device globals; no allocation) ----------------
__device__ __align__(16) float g_xn  [M * H];
__device__ __align__(16) float g_q   [M * NH * HD];
__device__ __align__(16) float g_k   [M * NKV * HD];
__device__ __align__(16) float g_v   [M * NKV * HD];
__device__ __align__(16) float g_attn[M * NH * HD];
__device__ __align__(16) float g_h2  [M * H];
__device__ __align__(16) float g_xn2 [M * H];
__device__ __align__(16) float g_g   [(size_t)M * IM];
__device__ __align__(16) float g_u   [(size_t)M * IM];

// ---------------- helpers ----------------
__device__ __forceinline__ uint32_t smem_u32(const void* p) {
    uint32_t a;
    asm("{ .reg .u64 t; cvta.to.shared.u64 t, %1; cvt.u32.u64 %0, t; }"
        : "=r"(a) : "l"(p));
    return a;
}

__device__ __forceinline__ void cp_async16(uint32_t dst, const void* src) {
    asm volatile("cp.async.cg.shared.global [%0], [%1], 16;"
                 :: "r"(dst), "l"(src));
}
#define CP_ASYNC_COMMIT() asm volatile("cp.async.commit_group;" ::: "memory")
#define CP_ASYNC_WAIT0()  asm volatile("cp.async.wait_group 0;" ::: "memory")

__device__ __forceinline__ void mma_tf32(float& c0, float& c1, float& c2, float& c3,
                                         uint32_t a0, uint32_t a1, uint32_t a2, uint32_t a3,
                                         uint32_t b0, uint32_t b1) {
    asm volatile(
        "mma.sync.aligned.m16n8k8.row.col.f32.tf32.tf32.f32 "
        "{%0,%1,%2,%3}, {%4,%5,%6,%7}, {%8,%9}, {%0,%1,%2,%3};"
        : "+f"(c0), "+f"(c1), "+f"(c2), "+f"(c3)
        : "r"(a0), "r"(a1), "r"(a2), "r"(a3), "r"(b0), "r"(b1));
}

__device__ __forceinline__ uint32_t tf32_rna(float x) {
    uint32_t r;
    asm("cvt.rna.tf32.f32 %0, %1;" : "=r"(r) : "f"(x));
    return r;
}

// ---------------- 3xTF32 GEMM core -----------------------------------------
// CTA tile 64x128, 256 threads (8 warps), warp tile 32x32, 2 CTAs/SM.
// C[m,n] = sum_k A[m,k]*Bm[n,k] (+res). K % 32 == 0.
#define GPAD 36
#define ABUF_FLOATS (64  * GPAD)                  // 2304
#define BBUF_FLOATS (128 * GPAD)                  // 4608
#define STAGE_FLOATS (ABUF_FLOATS + BBUF_FLOATS)  // 6912
#define GEMM_DSMEM  (2 * STAGE_FLOATS * 4)        // 55296 B

__device__ __forceinline__ void gemm_tile(float* sm,
                                          const float* __restrict__ A,
                                          const float* __restrict__ Bm,
                                          const float* __restrict__ res,
                                          float* __restrict__ C,
                                          int N, int K, int bm, int bn) {
    float* As[2] = { sm,               sm + STAGE_FLOATS };
    float* Bs[2] = { sm + ABUF_FLOATS, sm + STAGE_FLOATS + ABUF_FLOATS };
    const uint32_t smem_base = smem_u32(sm);

    const int tid  = threadIdx.x;
    const int wid  = tid >> 5;
    const int lane = tid & 31;
    const int wm   = wid >> 2;           // 0..1 -> 32-row band
    const int wn   = wid & 3;            // 0..3 -> 32-col band
    const int gid  = lane >> 2;          // 0..7
    const int tig  = lane & 3;           // 0..3
    const int KC   = K >> 5;
    const int lrow = tid >> 3;           // 0..31
    const int lc4  = tid & 7;            // 0..7

    float acc[2][4][4];
    #pragma unroll
    for (int i = 0; i < 2; i++)
        #pragma unroll
        for (int j = 0; j < 4; j++)
            #pragma unroll
            for (int l = 0; l < 4; l++) acc[i][j][l] = 0.f;

    auto issue_load = [&](int c, int buf) {
        const int k0 = c << 5;
        uint32_t abase = smem_base + (buf ? STAGE_FLOATS * 4 : 0);
        uint32_t bbase = abase + ABUF_FLOATS * 4;
        #pragma unroll
        for (int it = 0; it < 2; it++) {        // A: 64 rows
            int row = it * 32 + lrow;
            cp_async16(abase + (row * GPAD + lc4 * 4) * 4,
                       A + (size_t)(bm + row) * K + k0 + lc4 * 4);
        }
        #pragma unroll
        for (int it = 0; it < 4; it++) {        // B: 128 rows
            int row = it * 32 + lrow;
            cp_async16(bbase + (row * GPAD + lc4 * 4) * 4,
                       Bm + (size_t)(bn + row) * K + k0 + lc4 * 4);
        }
        CP_ASYNC_COMMIT();
    };

    issue_load(0, 0);

    for (int c = 0; c < KC; c++) {
        const int buf = c & 1;
        CP_ASYNC_WAIT0();
        __syncthreads();
        if (c + 1 < KC) issue_load(c + 1, buf ^ 1);

        const float* a_s = As[buf];
        const float* b_s = Bs[buf];

        #pragma unroll
        for (int ks = 0; ks < 4; ks++) {
            const int k0 = ks * 8;
            uint32_t ah[2][4], al[2][4];
            #pragma unroll
            for (int mt = 0; mt < 2; mt++) {
                int r0 = wm * 32 + mt * 16 + gid;
                float x0 = a_s[r0 * GPAD + k0 + tig];
                float x1 = a_s[(r0 + 8) * GPAD + k0 + tig];
                float x2 = a_s[r0 * GPAD + k0 + tig + 4];
                float x3 = a_s[(r0 + 8) * GPAD + k0 + tig + 4];
                ah[mt][0] = tf32_rna(x0); al[mt][0] = tf32_rna(x0 - __uint_as_float(ah[mt][0]));
                ah[mt][1] = tf32_rna(x1); al[mt][1] = tf32_rna(x1 - __uint_as_float(ah[mt][1]));
                ah[mt][2] = tf32_rna(x2); al[mt][2] = tf32_rna(x2 - __uint_as_float(ah[mt][2]));
                ah[mt][3] = tf32_rna(x3); al[mt][3] = tf32_rna(x3 - __uint_as_float(ah[mt][3]));
            }
            uint32_t bh[4][2], bl[4][2];
            #pragma unroll
            for (int nt = 0; nt < 4; nt++) {
                int nr = wn * 32 + nt * 8 + gid;
                float y0 = b_s[nr * GPAD + k0 + tig];
                float y1 = b_s[nr * GPAD + k0 + tig + 4];
                bh[nt][0] = tf32_rna(y0); bl[nt][0] = tf32_rna(y0 - __uint_as_float(bh[nt][0]));
                bh[nt][1] = tf32_rna(y1); bl[nt][1] = tf32_rna(y1 - __uint_as_float(bh[nt][1]));
            }
            #pragma unroll
            for (int mt = 0; mt < 2; mt++)
                #pragma unroll
                for (int nt = 0; nt < 4; nt++) {
                    mma_tf32(acc[mt][nt][0], acc[mt][nt][1],
                             acc[mt][nt][2], acc[mt][nt][3],
                             ah[mt][0], ah[mt][1], ah[mt][2], ah[mt][3],
                             bl[nt][0], bl[nt][1]);
                    mma_tf32(acc[mt][nt][0], acc[mt][nt][1],
                             acc[mt][nt][2], acc[mt][nt][3],
                             al[mt][0], al[mt][1], al[mt][2], al[mt][3],
                             bh[nt][0], bh[nt][1]);
                    mma_tf32(acc[mt][nt][0], acc[mt][nt][1],
                             acc[mt][nt][2], acc[mt][nt][3],
                             ah[mt][0], ah[mt][1], ah[mt][2], ah[mt][3],
                             bh[nt][0], bh[nt][1]);
                }
        }
        __syncthreads();
    }

    #pragma unroll
    for (int mt = 0; mt < 2; mt++) {
        int r0 = bm + wm * 32 + mt * 16 + gid;
        #pragma unroll
        for (int nt = 0; nt < 4; nt++) {
            int col = bn + wn * 32 + nt * 8 + tig * 2;
            size_t o0 = (size_t)r0 * N + col;
            size_t o1 = (size_t)(r0 + 8) * N + col;
            float2 v0 = make_float2(acc[mt][nt][0], acc[mt][nt][1]);
            float2 v1 = make_float2(acc[mt][nt][2], acc[mt][nt][3]);
            if (res) {
                float2 r0v = *(const float2*)(res + o0);
                float2 r1v = *(const float2*)(res + o1);
                v0.x += r0v.x; v0.y += r0v.y;
                v1.x += r1v.x; v1.y += r1v.y;
            }
            *(float2*)(C + o0) = v0;
            *(float2*)(C + o1) = v1;
        }
    }
}

// ---- generic GEMM (o-proj, down-proj) ----
__global__ void __launch_bounds__(256, 2)
gemm_mma_kernel(const float* __restrict__ A, const float* __restrict__ Bm,
                const float* __restrict__ res, float* __restrict__ C,
                int N, int K) {
    extern __shared__ float sm[];
    gemm_tile(sm, A, Bm, res, C, N, K, blockIdx.y * 64, blockIdx.x * 128);
}

// ---- fused QKV projection: blockIdx.x 0..15 Q, 16..19 K, 20..23 V ----
__global__ void __launch_bounds__(256, 2)
gemm_qkv_kernel(const float* __restrict__ A,
                const float* __restrict__ wq, const float* __restrict__ wk,
                const float* __restrict__ wv,
                float* __restrict__ q, float* __restrict__ k, float* __restrict__ v) {
    extern __shared__ float sm[];
    const int ct = blockIdx.x;
    const float* Bm; float* C; int N, bn;
    if (ct < 16)      { Bm = wq; C = q; N = NH  * HD; bn = ct * 128; }
    else if (ct < 20) { Bm = wk; C = k; N = NKV * HD; bn = (ct - 16) * 128; }
    else              { Bm = wv; C = v; N = NKV * HD; bn = (ct - 20) * 128; }
    gemm_tile(sm, A, Bm, nullptr, C, N, H, blockIdx.y * 64, bn);
}

// ---- fused gate/up: blockIdx.x 0..63 gate, 64..127 up ----
__global__ void __launch_bounds__(256, 2)
gemm_gu_kernel(const float* __restrict__ A,
               const float* __restrict__ wg, const float* __restrict__ wu,
               float* __restrict__ gg, float* __restrict__ uu) {
    extern __shared__ float sm[];
    const int ct = blockIdx.x;
    const float* Bm = (ct < 64) ? wg : wu;
    float* C        = (ct < 64) ? gg : uu;
    const int bn    = (ct & 63) * 128;
    gemm_tile(sm, A, Bm, nullptr, C, IM, H, blockIdx.y * 64, bn);
}

// ---------------- RMSNorm ----------------
__global__ void rmsnorm_kernel(const float* __restrict__ x,
                               const float* __restrict__ w,
                               float* __restrict__ out) {
    int row = blockIdx.x;
    const float* xr = x + (size_t)row * H;
    float ss = 0.f;
    for (int i = threadIdx.x; i < H / 4; i += blockDim.x) {
        float4 v = ((const float4*)xr)[i];
        ss += v.x * v.x + v.y * v.y + v.z * v.z + v.w * v.w;
    }
    __shared__ float red[32];
    #pragma unroll
    for (int o = 16; o; o >>= 1) ss += __shfl_xor_sync(0xffffffffu, ss, o);
    if ((threadIdx.x & 31) == 0) red[threadIdx.x >> 5] = ss;
    __syncthreads();
    if (threadIdx.x < 32) {
        float v = (threadIdx.x < (blockDim.x >> 5)) ? red[threadIdx.x] : 0.f;
        #pragma unroll
        for (int o = 16; o; o >>= 1) v += __shfl_xor_sync(0xffffffffu, v, o);
        if (threadIdx.x == 0) red[0] = v;
    }
    __syncthreads();
    float r = rsqrtf(red[0] / (float)H + 1e-6f);
    float* orow = out + (size_t)row * H;
    for (int i = threadIdx.x; i < H / 4; i += blockDim.x) {
        float4 v = ((const float4*)xr)[i];
        float4 wv = ((const float4*)w)[i];
        float4 o4 = make_float4(v.x * r * wv.x, v.y * r * wv.y,
                                v.z * r * wv.z, v.w * r * wv.w);
        ((float4*)orow)[i] = o4;
    }
}

// ---------------- RoPE ----------------
__global__ void rope_q_kernel(float* __restrict__ q,
                              const float* __restrict__ cosp,
                              const float* __restrict__ sinp,
                              const int* __restrict__ pos) {
    int idx = blockIdx.x * blockDim.x + threadIdx.x;
    int d2 = idx & 31;
    int h  = (idx >> 5) & (NH - 1);
    int bt = idx >> 10;
    int p  = pos[bt];
    float c = cosp[p * 32 + d2], s = sinp[p * 32 + d2];
    size_t base = (size_t)bt * (NH * HD) + h * HD + 2 * d2;
    float x1 = q[base], x2 = q[base + 1];
    q[base]     = x1 * c - x2 * s;
    q[base + 1] = x1 * s + x2 * c;
}

__global__ void rope_kv_kernel(float* __restrict__ k, const float* __restrict__ v,
                               const float* __restrict__ cosp,
                               const float* __restrict__ sinp,
                               const int* __restrict__ pos,
                               float* __restrict__ outk, float* __restrict__ outv) {
    int idx = blockIdx.x * blockDim.x + threadIdx.x;
    int d2 = idx & 31;
    int h  = (idx >> 5) & (NKV - 1);
    int bt = idx >> 8;
    int t  = bt & (T - 1);
    int b  = bt >> 10;
    int p  = pos[bt];
    float c = cosp[p * 32 + d2], s = sinp[p * 32 + d2];
    size_t base = (size_t)bt * (NKV * HD) + h * HD + 2 * d2;
    float x1 = k[base], x2 = k[base + 1];
    float r1 = x1 * c - x2 * s;
    float r2 = x1 * s + x2 * c;
    k[base] = r1; k[base + 1] = r2;
    size_t ob = (((size_t)(b * NKV + h)) * T + t) * HD + 2 * d2;
    outk[ob] = r1;       outk[ob + 1] = r2;
    outv[ob] = v[base];  outv[ob + 1] = v[base + 1];
}

// ---------------- Flash attention (64x64 tiles, fp32) ----------------
__global__ void __launch_bounds__(256)
attn_kernel(const float* __restrict__ Q, const float* __restrict__ Kg,
            const float* __restrict__ Vg, float* __restrict__ O) {
    __shared__ __align__(16) float QsT[64][64];
    __shared__ __align__(16) float KsT[64][64];
    __shared__ __align__(16) float Vs [64][64];
    float (*Ps)[64] = KsT;

    const int qt = blockIdx.x, h = blockIdx.y, b = blockIdx.z;
    const int kvh = h >> 2;
    const int tid = threadIdx.x;
    const int rg = tid >> 4, cg = tid & 15;
    const int m0 = rg * 4, n0 = cg * 4;

    {
        const int m = tid >> 2;
        const int d0 = (tid & 3) * 16;
        const float* qp = Q + ((size_t)(b * T + qt * 64 + m)) * (NH * HD) + h * HD + d0;
        #pragma unroll
        for (int i = 0; i < 16; i++) QsT[d0 + i][m] = qp[i];
    }

    float o_acc[4][4] = {};
    float row_max[4] = {-1e30f, -1e30f, -1e30f, -1e30f};
    float row_sum[4] = {0.f, 0.f, 0.f, 0.f};

    for (int kt = 0; kt <= qt; kt++) {
        __syncthreads();
        {
            const int n = tid >> 2;
            const int d0 = (tid & 3) * 16;
            const float* kp = Kg + ((size_t)(b * T + kt * 64 + n)) * (NKV * HD) + kvh * HD + d0;
            const float* vp = Vg + ((size_t)(b * T + kt * 64 + n)) * (NKV * HD) + kvh * HD + d0;
            #pragma unroll
            for (int i = 0; i < 16; i++) KsT[d0 + i][n] = kp[i];
            #pragma unroll
            for (int i = 0; i < 16; i += 4)
                *(float4*)&Vs[n][d0 + i] = *(const float4*)(vp + i);
        }
        __syncthreads();

        float s[4][4] = {};
        #pragma unroll 16
        for (int d = 0; d < 64; d++) {
            float4 av = *(const float4*)&QsT[d][m0];
            float4 bv = *(const float4*)&KsT[d][n0];
            float aa[4] = {av.x, av.y, av.z, av.w};
            float bb[4] = {bv.x, bv.y, bv.z, bv.w};
            #pragma unroll
            for (int i = 0; i < 4; i++)
                #pragma unroll
                for (int j = 0; j < 4; j++)
                    s[i][j] = fmaf(aa[i], bb[j], s[i][j]);
        }

        const float scale = 0.125f;
        if (kt == qt) {
            #pragma unroll
            for (int i = 0; i < 4; i++)
                #pragma unroll
                for (int j = 0; j < 4; j++)
                    s[i][j] = (n0 + j <= m0 + i) ? s[i][j] * scale : -1e30f;
        } else {
            #pragma unroll
            for (int i = 0; i < 4; i++)
                #pragma unroll
                for (int j = 0; j < 4; j++)
                    s[i][j] *= scale;
        }

        float p[4][4];
        #pragma unroll
        for (int i = 0; i < 4; i++) {
            float mx = fmaxf(fmaxf(s[i][0], s[i][1]), fmaxf(s[i][2], s[i][3]));
            #pragma unroll
            for (int o = 1; o < 16; o <<= 1)
                mx = fmaxf(mx, __shfl_xor_sync(0xffffffffu, mx, o));
            float nm = fmaxf(row_max[i], mx);
            float alpha = __expf(row_max[i] - nm);
            row_max[i] = nm;
            float rs = 0.f;
            #pragma unroll
            for (int j = 0; j < 4; j++) { p[i][j] = __expf(s[i][j] - nm); rs += p[i][j]; }
            #pragma unroll
            for (int o = 1; o < 16; o <<= 1)
                rs += __shfl_xor_sync(0xffffffffu, rs, o);
            row_sum[i] = row_sum[i] * alpha + rs;
            #pragma unroll
            for (int j = 0; j < 4; j++) o_acc[i][j] *= alpha;
        }

        __syncthreads();
        #pragma unroll
        for (int i = 0; i < 4; i++)
            #pragma unroll
            for (int j = 0; j < 4; j++)
                Ps[m0 + i][n0 + j] = p[i][j];
        __syncthreads();

        #pragma unroll 8
        for (int n = 0; n < 64; n++) {
            float4 vv = *(const float4*)&Vs[n][n0];
            float vb[4] = {vv.x, vv.y, vv.z, vv.w};
            #pragma unroll
            for (int i = 0; i < 4; i++) {
                float pv = Ps[m0 + i][n];
                #pragma unroll
                for (int j = 0; j < 4; j++)
                    o_acc[i][j] = fmaf(pv, vb[j], o_acc[i][j]);
            }
        }
    }

    #pragma unroll
    for (int i = 0; i < 4; i++) {
        float inv = 1.f / row_sum[i];
        int t = qt * 64 + m0 + i;
        float4 ov = make_float4(o_acc[i][0] * inv, o_acc[i][1] * inv,
                                o_acc[i][2] * inv, o_acc[i][3] * inv);
        *(float4*)(O + ((size_t)(b * T + t)) * (NH * HD) + h * HD + n0) = ov;
    }
}

// ---------------- SwiGLU elementwise ----------------
__global__ void silu_mul_kernel(float* __restrict__ g, const float* __restrict__ u) {
    int i = blockIdx.x * blockDim.x + threadIdx.x;
    float4 gv = ((const float4*)g)[i];
    float4 uv = ((const float4*)u)[i];
    gv.x = gv.x / (1.f + __expf(-gv.x)) * uv.x;
    gv.y = gv.y / (1.f + __expf(-gv.y)) * uv.y;
    gv.z = gv.z / (1.f + __expf(-gv.z)) * uv.z;
    gv.w = gv.w / (1.f + __expf(-gv.w)) * uv.w;
    ((float4*)g)[i] = gv;
}

// ---------------- launch ----------------
extern "C" void kernel_launch(void* const* d_in, const int* in_sizes, int n_in,
                              void* d_out, int out_size) {
    const float* hs   = (const float*)d_in[0];
    const float* cosp = (const float*)d_in[1];
    const float* sinp = (const float*)d_in[2];
    const int*   pos  = (const int*)  d_in[3];
    const float* n1w  = (const float*)d_in[5];
    const float* wq   = (const float*)d_in[6];
    const float* wk   = (const float*)d_in[7];
    const float* wv   = (const float*)d_in[8];
    const float* wo   = (const float*)d_in[9];
    const float* n2w  = (const float*)d_in[10];
    const float* wg   = (const float*)d_in[11];
    const float* wu   = (const float*)d_in[12];
    const float* wd   = (const float*)d_in[13];

    float *xn, *q, *k, *v, *attn, *h2, *xn2, *gg, *uu;
    cudaGetSymbolAddress((void**)&xn,   g_xn);
    cudaGetSymbolAddress((void**)&q,    g_q);
    cudaGetSymbolAddress((void**)&k,    g_k);
    cudaGetSymbolAddress((void**)&v,    g_v);
    cudaGetSymbolAddress((void**)&attn, g_attn);
    cudaGetSymbolAddress((void**)&h2,   g_h2);
    cudaGetSymbolAddress((void**)&xn2,  g_xn2);
    cudaGetSymbolAddress((void**)&gg,   g_g);
    cudaGetSymbolAddress((void**)&uu,   g_u);

    float* out_x = (float*)d_out;
    float* out_k = out_x + (size_t)M * H;
    float* out_v = out_k + (size_t)B * NKV * T * HD;

    cudaFuncSetAttribute(gemm_mma_kernel,
                         cudaFuncAttributeMaxDynamicSharedMemorySize, GEMM_DSMEM);
    cudaFuncSetAttribute(gemm_qkv_kernel,
                         cudaFuncAttributeMaxDynamicSharedMemorySize, GEMM_DSMEM);
    cudaFuncSetAttribute(gemm_gu_kernel,
                         cudaFuncAttributeMaxDynamicSharedMemorySize, GEMM_DSMEM);

    // 1. RMSNorm 1
    rmsnorm_kernel<<<M, 256>>>(hs, n1w, xn);
    // 2. fused Q/K/V projections
    gemm_qkv_kernel<<<dim3(24, M / 64), 256, GEMM_DSMEM>>>(xn, wq, wk, wv, q, k, v);
    // 3. RoPE + KV-cache writeout
    rope_q_kernel <<<(B * T * NH  * (HD / 2)) / 256, 256>>>(q, cosp, sinp, pos);
    rope_kv_kernel<<<(B * T * NKV * (HD / 2)) / 256, 256>>>(k, v, cosp, sinp, pos,
                                                            out_k, out_v);
    // 4. Attention
    attn_kernel<<<dim3(T / 64, NH, B), 256>>>(q, k, v, attn);
    // 5. O-projection + residual
    gemm_mma_kernel<<<dim3(H / 128, M / 64), 256, GEMM_DSMEM>>>(attn, wo, hs, h2, H, NH * HD);
    // 6. RMSNorm 2
    rmsnorm_kernel<<<M, 256>>>(h2, n2w, xn2);
    // 7. fused MLP gate/up
    gemm_gu_kernel<<<dim3(128, M / 64), 256, GEMM_DSMEM>>>(xn2, wg, wu, gg, uu);
    // 8. SwiGLU
    silu_mul_kernel<<<((size_t)M * IM / 4) / 256, 256>>>(gg, uu);
    // 9. Down projection + residual -> x output
    gemm_mma_kernel<<<dim3(H / 128, M / 64), 256, GEMM_DSMEM>>>(gg, wd, h2, out_x, H, IM);
}

// round 7
// speedup vs baseline: 1.8834x; 1.6717x over previous
#include <cuda_runtime.h>
#include <cuda_bf16.h>
#include <math.h>
#include <stdint.h>

#define B   2
#define T   1024
#define H   2048
#define NH  32
#define NKV 8
#define HD  64
#define IM  8192
#define M   (B*T)

typedef __nv_bfloat16  bf16;
typedef __nv_bfloat162 bf162;

// ---------------- scratch (device globals; no allocation) ----------------
// fp32 intermediates
__device__ __align__(16) float g_q  [M * NH * HD];
__device__ __align__(16) float g_k  [M * NKV * HD];
__device__ __align__(16) float g_v  [M * NKV * HD];
__device__ __align__(16) float g_h2 [M * H];
__device__ __align__(16) float g_gg [(size_t)M * IM];
__device__ __align__(16) float g_uu [(size_t)M * IM];
// bf16 hi/lo split weights
__device__ __align__(16) bf16 s_wq_h[NH*HD*H],  s_wq_l[NH*HD*H];
__device__ __align__(16) bf16 s_wk_h[NKV*HD*H], s_wk_l[NKV*HD*H];
__device__ __align__(16) bf16 s_wv_h[NKV*HD*H], s_wv_l[NKV*HD*H];
__device__ __align__(16) bf16 s_wo_h[H*NH*HD],  s_wo_l[H*NH*HD];
__device__ __align__(16) bf16 s_wg_h[(size_t)IM*H], s_wg_l[(size_t)IM*H];
__device__ __align__(16) bf16 s_wu_h[(size_t)IM*H], s_wu_l[(size_t)IM*H];
__device__ __align__(16) bf16 s_wd_h[(size_t)H*IM], s_wd_l[(size_t)H*IM];
// bf16 hi/lo split activations
__device__ __align__(16) bf16 s_xn_h [M*H],        s_xn_l [M*H];
__device__ __align__(16) bf16 s_at_h [M*NH*HD],    s_at_l [M*NH*HD];
__device__ __align__(16) bf16 s_xn2_h[M*H],        s_xn2_l[M*H];
__device__ __align__(16) bf16 s_g_h  [(size_t)M*IM], s_g_l[(size_t)M*IM];

// ---------------- helpers ----------------
__device__ __forceinline__ uint32_t smem_u32(const void* p) {
    uint32_t a;
    asm("{ .reg .u64 t; cvta.to.shared.u64 t, %1; cvt.u32.u64 %0, t; }"
        : "=r"(a) : "l"(p));
    return a;
}
__device__ __forceinline__ void cp_async16(uint32_t dst, const void* src) {
    asm volatile("cp.async.cg.shared.global [%0], [%1], 16;"
                 :: "r"(dst), "l"(src));
}
#define CP_ASYNC_COMMIT() asm volatile("cp.async.commit_group;" ::: "memory")
#define CP_ASYNC_WAIT0()  asm volatile("cp.async.wait_group 0;" ::: "memory")

__device__ __forceinline__ void mma_bf16(float& c0, float& c1, float& c2, float& c3,
                                         uint32_t a0, uint32_t a1, uint32_t a2, uint32_t a3,
                                         uint32_t b0, uint32_t b1) {
    asm volatile(
        "mma.sync.aligned.m16n8k16.row.col.f32.bf16.bf16.f32 "
        "{%0,%1,%2,%3}, {%4,%5,%6,%7}, {%8,%9}, {%0,%1,%2,%3};"
        : "+f"(c0), "+f"(c1), "+f"(c2), "+f"(c3)
        : "r"(a0), "r"(a1), "r"(a2), "r"(a3), "r"(b0), "r"(b1));
}

// split-store 4 consecutive fp32 -> hi/lo bf16 arrays at element index idx (4-aligned)
__device__ __forceinline__ void split_store4(bf16* __restrict__ h, bf16* __restrict__ l,
                                             size_t idx, float x, float y, float z, float w) {
    bf162 h0 = __floats2bfloat162_rn(x, y);
    bf162 h1 = __floats2bfloat162_rn(z, w);
    float lx = x - __bfloat162float(__low2bfloat16(h0));
    float ly = y - __bfloat162float(__high2bfloat16(h0));
    float lz = z - __bfloat162float(__low2bfloat16(h1));
    float lw = w - __bfloat162float(__high2bfloat16(h1));
    *(bf162*)(h + idx)     = h0;
    *(bf162*)(h + idx + 2) = h1;
    *(bf162*)(l + idx)     = __floats2bfloat162_rn(lx, ly);
    *(bf162*)(l + idx + 2) = __floats2bfloat162_rn(lz, lw);
}

// ---------------- weight split kernel ----------------
__global__ void split_kernel(const float* __restrict__ x,
                             bf16* __restrict__ h, bf16* __restrict__ l, int n4) {
    int i = blockIdx.x * blockDim.x + threadIdx.x;
    if (i >= n4) return;
    float4 v = ((const float4*)x)[i];
    split_store4(h, l, (size_t)i * 4, v.x, v.y, v.z, v.w);
}

// ---------------- 3xBF16 GEMM core -----------------------------------------
// CTA tile 64x128, 256 threads (8 warps), warp tile 32x32, 2 CTAs/SM.
// A/B given as pre-split bf16 hi/lo, [rows][K] row-major. K % 32 == 0.
#define RPAD 20                                   // uints per 32-elem row (16 data + 4 pad)
#define ATILE_U (64 * RPAD)                       // 1280
#define BTILE_U (128 * RPAD)                      // 2560
#define STAGE_U (2 * ATILE_U + 2 * BTILE_U)       // 7680 uints = 30720 B
#define GEMM_DSMEM (2 * STAGE_U * 4)              // 61440 B

__device__ __forceinline__ void gemm_tile(float* sm,
                                          const bf16* __restrict__ Ah, const bf16* __restrict__ Al,
                                          const bf16* __restrict__ Bh, const bf16* __restrict__ Bl,
                                          const float* __restrict__ res, float* __restrict__ C,
                                          int N, int K, int bm, int bn) {
    const uint32_t smem_base = smem_u32(sm);
    const int tid  = threadIdx.x;
    const int wid  = tid >> 5;
    const int lane = tid & 31;
    const int wm   = wid >> 2;           // 0..1 -> 32-row band
    const int wn   = wid & 3;            // 0..3 -> 32-col band
    const int gid  = lane >> 2;          // 0..7
    const int tig  = lane & 3;           // 0..3
    const int KC   = K >> 5;
    const int lrow = tid >> 2;           // 0..63
    const int lch  = tid & 3;            // 0..3 (16B chunk within 64B row)

    float acc[2][4][4];
    #pragma unroll
    for (int i = 0; i < 2; i++)
        #pragma unroll
        for (int j = 0; j < 4; j++)
            #pragma unroll
            for (int k = 0; k < 4; k++) acc[i][j][k] = 0.f;

    auto issue_load = [&](int c, int buf) {
        const int k0 = c << 5;
        uint32_t st = smem_base + buf * (STAGE_U * 4);
        // A hi/lo: 64 rows x 32 bf16
        cp_async16(st + (lrow * RPAD + lch * 4) * 4,
                   Ah + (size_t)(bm + lrow) * K + k0 + lch * 8);
        cp_async16(st + (ATILE_U + lrow * RPAD + lch * 4) * 4,
                   Al + (size_t)(bm + lrow) * K + k0 + lch * 8);
        // B hi/lo: 128 rows
        #pragma unroll
        for (int it = 0; it < 2; it++) {
            int br = it * 64 + lrow;
            cp_async16(st + (2 * ATILE_U + br * RPAD + lch * 4) * 4,
                       Bh + (size_t)(bn + br) * K + k0 + lch * 8);
            cp_async16(st + (2 * ATILE_U + BTILE_U + br * RPAD + lch * 4) * 4,
                       Bl + (size_t)(bn + br) * K + k0 + lch * 8);
        }
        CP_ASYNC_COMMIT();
    };

    issue_load(0, 0);

    for (int c = 0; c < KC; c++) {
        const int buf = c & 1;
        CP_ASYNC_WAIT0();
        __syncthreads();
        if (c + 1 < KC) issue_load(c + 1, buf ^ 1);

        const uint32_t* base_u = (const uint32_t*)sm + buf * STAGE_U;
        const uint32_t* ah_s = base_u;
        const uint32_t* al_s = base_u + ATILE_U;
        const uint32_t* bh_s = base_u + 2 * ATILE_U;
        const uint32_t* bl_s = bh_s + BTILE_U;

        #pragma unroll
        for (int ks = 0; ks < 2; ks++) {
            const int kc = ks * 8;
            uint32_t ahf[2][4], alf[2][4];
            #pragma unroll
            for (int mt = 0; mt < 2; mt++) {
                int i0 = (wm * 32 + mt * 16 + gid) * RPAD + kc + tig;
                int i1 = i0 + 8 * RPAD;
                ahf[mt][0] = ah_s[i0];     ahf[mt][1] = ah_s[i1];
                ahf[mt][2] = ah_s[i0 + 4]; ahf[mt][3] = ah_s[i1 + 4];
                alf[mt][0] = al_s[i0];     alf[mt][1] = al_s[i1];
                alf[mt][2] = al_s[i0 + 4]; alf[mt][3] = al_s[i1 + 4];
            }
            uint32_t bhf[4][2], blf[4][2];
            #pragma unroll
            for (int nt = 0; nt < 4; nt++) {
                int ib = (wn * 32 + nt * 8 + gid) * RPAD + kc + tig;
                bhf[nt][0] = bh_s[ib]; bhf[nt][1] = bh_s[ib + 4];
                blf[nt][0] = bl_s[ib]; blf[nt][1] = bl_s[ib + 4];
            }
            #pragma unroll
            for (int mt = 0; mt < 2; mt++)
                #pragma unroll
                for (int nt = 0; nt < 4; nt++) {
                    mma_bf16(acc[mt][nt][0], acc[mt][nt][1],
                             acc[mt][nt][2], acc[mt][nt][3],
                             ahf[mt][0], ahf[mt][1], ahf[mt][2], ahf[mt][3],
                             blf[nt][0], blf[nt][1]);
                    mma_bf16(acc[mt][nt][0], acc[mt][nt][1],
                             acc[mt][nt][2], acc[mt][nt][3],
                             alf[mt][0], alf[mt][1], alf[mt][2], alf[mt][3],
                             bhf[nt][0], bhf[nt][1]);
                    mma_bf16(acc[mt][nt][0], acc[mt][nt][1],
                             acc[mt][nt][2], acc[mt][nt][3],
                             ahf[mt][0], ahf[mt][1], ahf[mt][2], ahf[mt][3],
                             bhf[nt][0], bhf[nt][1]);
                }
        }
        __syncthreads();
    }

    #pragma unroll
    for (int mt = 0; mt < 2; mt++) {
        int r0 = bm + wm * 32 + mt * 16 + gid;
        #pragma unroll
        for (int nt = 0; nt < 4; nt++) {
            int col = bn + wn * 32 + nt * 8 + tig * 2;
            size_t o0 = (size_t)r0 * N + col;
            size_t o1 = (size_t)(r0 + 8) * N + col;
            float2 v0 = make_float2(acc[mt][nt][0], acc[mt][nt][1]);
            float2 v1 = make_float2(acc[mt][nt][2], acc[mt][nt][3]);
            if (res) {
                float2 r0v = *(const float2*)(res + o0);
                float2 r1v = *(const float2*)(res + o1);
                v0.x += r0v.x; v0.y += r0v.y;
                v1.x += r1v.x; v1.y += r1v.y;
            }
            *(float2*)(C + o0) = v0;
            *(float2*)(C + o1) = v1;
        }
    }
}

// ---- generic GEMM (o-proj, down-proj) ----
__global__ void __launch_bounds__(256, 2)
gemm_mma_kernel(const bf16* __restrict__ Ah, const bf16* __restrict__ Al,
                const bf16* __restrict__ Bh, const bf16* __restrict__ Bl,
                const float* __restrict__ res, float* __restrict__ C,
                int N, int K) {
    extern __shared__ float sm[];
    gemm_tile(sm, Ah, Al, Bh, Bl, res, C, N, K, blockIdx.y * 64, blockIdx.x * 128);
}

// ---- fused QKV projection: blockIdx.x 0..15 Q, 16..19 K, 20..23 V ----
__global__ void __launch_bounds__(256, 2)
gemm_qkv_kernel(const bf16* __restrict__ Ah, const bf16* __restrict__ Al,
                float* __restrict__ q, float* __restrict__ k, float* __restrict__ v) {
    extern __shared__ float sm[];
    const int ct = blockIdx.x;
    const bf16 *Bh, *Bl; float* C; int N, bn;
    if (ct < 16)      { Bh = s_wq_h; Bl = s_wq_l; C = q; N = NH  * HD; bn = ct * 128; }
    else if (ct < 20) { Bh = s_wk_h; Bl = s_wk_l; C = k; N = NKV * HD; bn = (ct - 16) * 128; }
    else              { Bh = s_wv_h; Bl = s_wv_l; C = v; N = NKV * HD; bn = (ct - 20) * 128; }
    gemm_tile(sm, Ah, Al, Bh, Bl, nullptr, C, N, H, blockIdx.y * 64, bn);
}

// ---- fused gate/up: blockIdx.x 0..63 gate, 64..127 up ----
__global__ void __launch_bounds__(256, 2)
gemm_gu_kernel(const bf16* __restrict__ Ah, const bf16* __restrict__ Al,
               float* __restrict__ gg, float* __restrict__ uu) {
    extern __shared__ float sm[];
    const int ct = blockIdx.x;
    const bf16* Bh = (ct < 64) ? s_wg_h : s_wu_h;
    const bf16* Bl = (ct < 64) ? s_wg_l : s_wu_l;
    float* C       = (ct < 64) ? gg : uu;
    const int bn   = (ct & 63) * 128;
    gemm_tile(sm, Ah, Al, Bh, Bl, nullptr, C, IM, H, blockIdx.y * 64, bn);
}

// ---------------- RMSNorm with split output ----------------
__global__ void rmsnorm_split_kernel(const float* __restrict__ x,
                                     const float* __restrict__ w,
                                     bf16* __restrict__ oh, bf16* __restrict__ ol) {
    int row = blockIdx.x;
    const float* xr = x + (size_t)row * H;
    float ss = 0.f;
    for (int i = threadIdx.x; i < H / 4; i += blockDim.x) {
        float4 v = ((const float4*)xr)[i];
        ss += v.x * v.x + v.y * v.y + v.z * v.z + v.w * v.w;
    }
    __shared__ float red[32];
    #pragma unroll
    for (int o = 16; o; o >>= 1) ss += __shfl_xor_sync(0xffffffffu, ss, o);
    if ((threadIdx.x & 31) == 0) red[threadIdx.x >> 5] = ss;
    __syncthreads();
    if (threadIdx.x < 32) {
        float v = (threadIdx.x < (blockDim.x >> 5)) ? red[threadIdx.x] : 0.f;
        #pragma unroll
        for (int o = 16; o; o >>= 1) v += __shfl_xor_sync(0xffffffffu, v, o);
        if (threadIdx.x == 0) red[0] = v;
    }
    __syncthreads();
    float r = rsqrtf(red[0] / (float)H + 1e-6f);
    for (int i = threadIdx.x; i < H / 4; i += blockDim.x) {
        float4 v = ((const float4*)xr)[i];
        float4 wv = ((const float4*)w)[i];
        split_store4(oh, ol, (size_t)row * H + 4 * i,
                     v.x * r * wv.x, v.y * r * wv.y, v.z * r * wv.z, v.w * r * wv.w);
    }
}

// ---------------- RoPE ----------------
__global__ void rope_q_kernel(float* __restrict__ q,
                              const float* __restrict__ cosp,
                              const float* __restrict__ sinp,
                              const int* __restrict__ pos) {
    int idx = blockIdx.x * blockDim.x + threadIdx.x;
    int d2 = idx & 31;
    int h  = (idx >> 5) & (NH - 1);
    int bt = idx >> 10;
    int p  = pos[bt];
    float c = cosp[p * 32 + d2], s = sinp[p * 32 + d2];
    size_t base = (size_t)bt * (NH * HD) + h * HD + 2 * d2;
    float x1 = q[base], x2 = q[base + 1];
    q[base]     = x1 * c - x2 * s;
    q[base + 1] = x1 * s + x2 * c;
}

__global__ void rope_kv_kernel(float* __restrict__ k, const float* __restrict__ v,
                               const float* __restrict__ cosp,
                               const float* __restrict__ sinp,
                               const int* __restrict__ pos,
                               float* __restrict__ outk, float* __restrict__ outv) {
    int idx = blockIdx.x * blockDim.x + threadIdx.x;
    int d2 = idx & 31;
    int h  = (idx >> 5) & (NKV - 1);
    int bt = idx >> 8;
    int t  = bt & (T - 1);
    int b  = bt >> 10;
    int p  = pos[bt];
    float c = cosp[p * 32 + d2], s = sinp[p * 32 + d2];
    size_t base = (size_t)bt * (NKV * HD) + h * HD + 2 * d2;
    float x1 = k[base], x2 = k[base + 1];
    float r1 = x1 * c - x2 * s;
    float r2 = x1 * s + x2 * c;
    k[base] = r1; k[base + 1] = r2;
    size_t ob = (((size_t)(b * NKV + h)) * T + t) * HD + 2 * d2;
    outk[ob] = r1;       outk[ob + 1] = r2;
    outv[ob] = v[base];  outv[ob + 1] = v[base + 1];
}

// ---------------- Flash attention (64x64 tiles, fp32, split output) --------
__global__ void __launch_bounds__(256)
attn_kernel(const float* __restrict__ Q, const float* __restrict__ Kg,
            const float* __restrict__ Vg,
            bf16* __restrict__ Oh, bf16* __restrict__ Ol) {
    __shared__ __align__(16) float QsT[64][64];
    __shared__ __align__(16) float KsT[64][64];
    __shared__ __align__(16) float Vs [64][64];
    float (*Ps)[64] = KsT;

    const int qt = blockIdx.x, h = blockIdx.y, b = blockIdx.z;
    const int kvh = h >> 2;
    const int tid = threadIdx.x;
    const int rg = tid >> 4, cg = tid & 15;
    const int m0 = rg * 4, n0 = cg * 4;

    {
        const int m = tid >> 2;
        const int d0 = (tid & 3) * 16;
        const float* qp = Q + ((size_t)(b * T + qt * 64 + m)) * (NH * HD) + h * HD + d0;
        #pragma unroll
        for (int i = 0; i < 16; i++) QsT[d0 + i][m] = qp[i];
    }

    float o_acc[4][4] = {};
    float row_max[4] = {-1e30f, -1e30f, -1e30f, -1e30f};
    float row_sum[4] = {0.f, 0.f, 0.f, 0.f};

    for (int kt = 0; kt <= qt; kt++) {
        __syncthreads();
        {
            const int n = tid >> 2;
            const int d0 = (tid & 3) * 16;
            const float* kp = Kg + ((size_t)(b * T + kt * 64 + n)) * (NKV * HD) + kvh * HD + d0;
            const float* vp = Vg + ((size_t)(b * T + kt * 64 + n)) * (NKV * HD) + kvh * HD + d0;
            #pragma unroll
            for (int i = 0; i < 16; i++) KsT[d0 + i][n] = kp[i];
            #pragma unroll
            for (int i = 0; i < 16; i += 4)
                *(float4*)&Vs[n][d0 + i] = *(const float4*)(vp + i);
        }
        __syncthreads();

        float s[4][4] = {};
        #pragma unroll 16
        for (int d = 0; d < 64; d++) {
            float4 av = *(const float4*)&QsT[d][m0];
            float4 bv = *(const float4*)&KsT[d][n0];
            float aa[4] = {av.x, av.y, av.z, av.w};
            float bb[4] = {bv.x, bv.y, bv.z, bv.w};
            #pragma unroll
            for (int i = 0; i < 4; i++)
                #pragma unroll
                for (int j = 0; j < 4; j++)
                    s[i][j] = fmaf(aa[i], bb[j], s[i][j]);
        }

        const float scale = 0.125f;
        if (kt == qt) {
            #pragma unroll
            for (int i = 0; i < 4; i++)
                #pragma unroll
                for (int j = 0; j < 4; j++)
                    s[i][j] = (n0 + j <= m0 + i) ? s[i][j] * scale : -1e30f;
        } else {
            #pragma unroll
            for (int i = 0; i < 4; i++)
                #pragma unroll
                for (int j = 0; j < 4; j++)
                    s[i][j] *= scale;
        }

        float p[4][4];
        #pragma unroll
        for (int i = 0; i < 4; i++) {
            float mx = fmaxf(fmaxf(s[i][0], s[i][1]), fmaxf(s[i][2], s[i][3]));
            #pragma unroll
            for (int o = 1; o < 16; o <<= 1)
                mx = fmaxf(mx, __shfl_xor_sync(0xffffffffu, mx, o));
            float nm = fmaxf(row_max[i], mx);
            float alpha = __expf(row_max[i] - nm);
            row_max[i] = nm;
            float rs = 0.f;
            #pragma unroll
            for (int j = 0; j < 4; j++) { p[i][j] = __expf(s[i][j] - nm); rs += p[i][j]; }
            #pragma unroll
            for (int o = 1; o < 16; o <<= 1)
                rs += __shfl_xor_sync(0xffffffffu, rs, o);
            row_sum[i] = row_sum[i] * alpha + rs;
            #pragma unroll
            for (int j = 0; j < 4; j++) o_acc[i][j] *= alpha;
        }

        __syncthreads();
        #pragma unroll
        for (int i = 0; i < 4; i++)
            #pragma unroll
            for (int j = 0; j < 4; j++)
                Ps[m0 + i][n0 + j] = p[i][j];
        __syncthreads();

        #pragma unroll 8
        for (int n = 0; n < 64; n++) {
            float4 vv = *(const float4*)&Vs[n][n0];
            float vb[4] = {vv.x, vv.y, vv.z, vv.w};
            #pragma unroll
            for (int i = 0; i < 4; i++) {
                float pv = Ps[m0 + i][n];
                #pragma unroll
                for (int j = 0; j < 4; j++)
                    o_acc[i][j] = fmaf(pv, vb[j], o_acc[i][j]);
            }
        }
    }

    #pragma unroll
    for (int i = 0; i < 4; i++) {
        float inv = 1.f / row_sum[i];
        int t = qt * 64 + m0 + i;
        size_t off = ((size_t)(b * T + t)) * (NH * HD) + h * HD + n0;
        split_store4(Oh, Ol, off,
                     o_acc[i][0] * inv, o_acc[i][1] * inv,
                     o_acc[i][2] * inv, o_acc[i][3] * inv);
    }
}

// ---------------- SwiGLU elementwise with split output ----------------
__global__ void silu_mul_split_kernel(const float* __restrict__ g,
                                      const float* __restrict__ u,
                                      bf16* __restrict__ oh, bf16* __restrict__ ol) {
    size_t i = (size_t)blockIdx.x * blockDim.x + threadIdx.x;
    float4 gv = ((const float4*)g)[i];
    float4 uv = ((const float4*)u)[i];
    float rx = gv.x / (1.f + __expf(-gv.x)) * uv.x;
    float ry = gv.y / (1.f + __expf(-gv.y)) * uv.y;
    float rz = gv.z / (1.f + __expf(-gv.z)) * uv.z;
    float rw = gv.w / (1.f + __expf(-gv.w)) * uv.w;
    split_store4(oh, ol, i * 4, rx, ry, rz, rw);
}

// ---------------- launch ----------------
extern "C" void kernel_launch(void* const* d_in, const int* in_sizes, int n_in,
                              void* d_out, int out_size) {
    const float* hs   = (const float*)d_in[0];
    const float* cosp = (const float*)d_in[1];
    const float* sinp = (const float*)d_in[2];
    const int*   pos  = (const int*)  d_in[3];
    const float* n1w  = (const float*)d_in[5];
    const float* wq   = (const float*)d_in[6];
    const float* wk   = (const float*)d_in[7];
    const float* wv   = (const float*)d_in[8];
    const float* wo   = (const float*)d_in[9];
    const float* n2w  = (const float*)d_in[10];
    const float* wg   = (const float*)d_in[11];
    const float* wu   = (const float*)d_in[12];
    const float* wd   = (const float*)d_in[13];

    float *q, *k, *v, *h2, *gg, *uu;
    cudaGetSymbolAddress((void**)&q,  g_q);
    cudaGetSymbolAddress((void**)&k,  g_k);
    cudaGetSymbolAddress((void**)&v,  g_v);
    cudaGetSymbolAddress((void**)&h2, g_h2);
    cudaGetSymbolAddress((void**)&gg, g_gg);
    cudaGetSymbolAddress((void**)&uu, g_uu);

    bf16 *wqh,*wql,*wkh,*wkl,*wvh,*wvl,*woh,*wol,*wgh,*wgl,*wuh,*wul,*wdh,*wdl;
    bf16 *xnh,*xnl,*ath,*atl,*xn2h,*xn2l,*gh,*gl;
    cudaGetSymbolAddress((void**)&wqh, s_wq_h);  cudaGetSymbolAddress((void**)&wql, s_wq_l);
    cudaGetSymbolAddress((void**)&wkh, s_wk_h);  cudaGetSymbolAddress((void**)&wkl, s_wk_l);
    cudaGetSymbolAddress((void**)&wvh, s_wv_h);  cudaGetSymbolAddress((void**)&wvl, s_wv_l);
    cudaGetSymbolAddress((void**)&woh, s_wo_h);  cudaGetSymbolAddress((void**)&wol, s_wo_l);
    cudaGetSymbolAddress((void**)&wgh, s_wg_h);  cudaGetSymbolAddress((void**)&wgl, s_wg_l);
    cudaGetSymbolAddress((void**)&wuh, s_wu_h);  cudaGetSymbolAddress((void**)&wul, s_wu_l);
    cudaGetSymbolAddress((void**)&wdh, s_wd_h);  cudaGetSymbolAddress((void**)&wdl, s_wd_l);
    cudaGetSymbolAddress((void**)&xnh, s_xn_h);  cudaGetSymbolAddress((void**)&xnl, s_xn_l);
    cudaGetSymbolAddress((void**)&ath, s_at_h);  cudaGetSymbolAddress((void**)&atl, s_at_l);
    cudaGetSymbolAddress((void**)&xn2h, s_xn2_h);cudaGetSymbolAddress((void**)&xn2l, s_xn2_l);
    cudaGetSymbolAddress((void**)&gh,  s_g_h);   cudaGetSymbolAddress((void**)&gl,  s_g_l);

    float* out_x = (float*)d_out;
    float* out_k = out_x + (size_t)M * H;
    float* out_v = out_k + (size_t)B * NKV * T * HD;

    cudaFuncSetAttribute(gemm_mma_kernel,
                         cudaFuncAttributeMaxDynamicSharedMemorySize, GEMM_DSMEM);
    cudaFuncSetAttribute(gemm_qkv_kernel,
                         cudaFuncAttributeMaxDynamicSharedMemorySize, GEMM_DSMEM);
    cudaFuncSetAttribute(gemm_gu_kernel,
                         cudaFuncAttributeMaxDynamicSharedMemorySize, GEMM_DSMEM);

    // 0. split weights (hi/lo bf16)
    split_kernel<<<(NH*HD*H/4 + 255)/256, 256>>>(wq, wqh, wql, NH*HD*H/4);
    split_kernel<<<(NKV*HD*H/4 + 255)/256, 256>>>(wk, wkh, wkl, NKV*HD*H/4);
    split_kernel<<<(NKV*HD*H/4 + 255)/256, 256>>>(wv, wvh, wvl, NKV*HD*H/4);
    split_kernel<<<(H*NH*HD/4 + 255)/256, 256>>>(wo, woh, wol, H*NH*HD/4);
    split_kernel<<<(IM*H/4 + 255)/256, 256>>>(wg, wgh, wgl, IM*H/4);
    split_kernel<<<(IM*H/4 + 255)/256, 256>>>(wu, wuh, wul, IM*H/4);
    split_kernel<<<(H*IM/4 + 255)/256, 256>>>(wd, wdh, wdl, H*IM/4);

    // 1. RMSNorm 1 (split output)
    rmsnorm_split_kernel<<<M, 256>>>(hs, n1w, xnh, xnl);
    // 2. fused Q/K/V projections
    gemm_qkv_kernel<<<dim3(24, M / 64), 256, GEMM_DSMEM>>>(xnh, xnl, q, k, v);
    // 3. RoPE + KV-cache writeout
    rope_q_kernel <<<(B * T * NH  * (HD / 2)) / 256, 256>>>(q, cosp, sinp, pos);
    rope_kv_kernel<<<(B * T * NKV * (HD / 2)) / 256, 256>>>(k, v, cosp, sinp, pos,
                                                            out_k, out_v);
    // 4. Attention (split output)
    attn_kernel<<<dim3(T / 64, NH, B), 256>>>(q, k, v, ath, atl);
    // 5. O-projection + residual
    gemm_mma_kernel<<<dim3(H / 128, M / 64), 256, GEMM_DSMEM>>>(ath, atl, woh, wol,
                                                                hs, h2, H, NH * HD);
    // 6. RMSNorm 2 (split output)
    rmsnorm_split_kernel<<<M, 256>>>(h2, n2w, xn2h, xn2l);
    // 7. fused MLP gate/up
    gemm_gu_kernel<<<dim3(128, M / 64), 256, GEMM_DSMEM>>>(xn2h, xn2l, gg, uu);
    // 8. SwiGLU (split output)
    silu_mul_split_kernel<<<((size_t)M * IM / 4) / 256, 256>>>(gg, uu, gh, gl);
    // 9. Down projection + residual -> x output
    gemm_mma_kernel<<<dim3(H / 128, M / 64), 256, GEMM_DSMEM>>>(gh, gl, wdh, wdl,
                                                                h2, out_x, H, IM);
}

// round 8
// speedup vs baseline: 2.1294x; 1.1306x over previous
#include <cuda_runtime.h>
#include <cuda_bf16.h>
#include <math.h>
#include <stdint.h>

#define B   2
#define T   1024
#define H   2048
#define NH  32
#define NKV 8
#define HD  64
#define IM  8192
#define M   (B*T)

typedef __nv_bfloat16  bf16;
typedef __nv_bfloat162 bf162;

// ---------------- scratch (device globals; no allocation) ----------------
__device__ __align__(16) float g_q  [M * NH * HD];
__device__ __align__(16) float g_k  [M * NKV * HD];
__device__ __align__(16) float g_v  [M * NKV * HD];
__device__ __align__(16) float g_h2 [M * H];
__device__ __align__(16) float g_gg [(size_t)M * IM];
__device__ __align__(16) float g_uu [(size_t)M * IM];
// bf16 hi/lo split weights
__device__ __align__(16) bf16 s_wq_h[NH*HD*H],  s_wq_l[NH*HD*H];
__device__ __align__(16) bf16 s_wk_h[NKV*HD*H], s_wk_l[NKV*HD*H];
__device__ __align__(16) bf16 s_wv_h[NKV*HD*H], s_wv_l[NKV*HD*H];
__device__ __align__(16) bf16 s_wo_h[H*NH*HD],  s_wo_l[H*NH*HD];
__device__ __align__(16) bf16 s_wg_h[(size_t)IM*H], s_wg_l[(size_t)IM*H];
__device__ __align__(16) bf16 s_wu_h[(size_t)IM*H], s_wu_l[(size_t)IM*H];
__device__ __align__(16) bf16 s_wd_h[(size_t)H*IM], s_wd_l[(size_t)H*IM];
// bf16 hi/lo split activations
__device__ __align__(16) bf16 s_xn_h [M*H],        s_xn_l [M*H];
__device__ __align__(16) bf16 s_at_h [M*NH*HD],    s_at_l [M*NH*HD];
__device__ __align__(16) bf16 s_xn2_h[M*H],        s_xn2_l[M*H];
__device__ __align__(16) bf16 s_g_h  [(size_t)M*IM], s_g_l[(size_t)M*IM];

// ---------------- helpers ----------------
__device__ __forceinline__ uint32_t smem_u32(const void* p) {
    uint32_t a;
    asm("{ .reg .u64 t; cvta.to.shared.u64 t, %1; cvt.u32.u64 %0, t; }"
        : "=r"(a) : "l"(p));
    return a;
}
__device__ __forceinline__ void cp_async16(uint32_t dst, const void* src) {
    asm volatile("cp.async.cg.shared.global [%0], [%1], 16;"
                 :: "r"(dst), "l"(src));
}
#define CP_ASYNC_COMMIT() asm volatile("cp.async.commit_group;" ::: "memory")
#define CP_ASYNC_WAIT0()  asm volatile("cp.async.wait_group 0;" ::: "memory")

#define LDMX4(r0, r1, r2, r3, addr) \
    asm volatile("ldmatrix.sync.aligned.m8n8.x4.shared.b16 {%0,%1,%2,%3}, [%4];" \
        : "=r"(r0), "=r"(r1), "=r"(r2), "=r"(r3) : "r"(addr))

__device__ __forceinline__ void mma_bf16(float& c0, float& c1, float& c2, float& c3,
                                         uint32_t a0, uint32_t a1, uint32_t a2, uint32_t a3,
                                         uint32_t b0, uint32_t b1) {
    asm volatile(
        "mma.sync.aligned.m16n8k16.row.col.f32.bf16.bf16.f32 "
        "{%0,%1,%2,%3}, {%4,%5,%6,%7}, {%8,%9}, {%0,%1,%2,%3};"
        : "+f"(c0), "+f"(c1), "+f"(c2), "+f"(c3)
        : "r"(a0), "r"(a1), "r"(a2), "r"(a3), "r"(b0), "r"(b1));
}

// split-store 4 consecutive fp32 -> hi/lo bf16 arrays
__device__ __forceinline__ void split_store4(bf16* __restrict__ h, bf16* __restrict__ l,
                                             size_t idx, float x, float y, float z, float w) {
    bf162 h0 = __floats2bfloat162_rn(x, y);
    bf162 h1 = __floats2bfloat162_rn(z, w);
    float lx = x - __bfloat162float(__low2bfloat16(h0));
    float ly = y - __bfloat162float(__high2bfloat16(h0));
    float lz = z - __bfloat162float(__low2bfloat16(h1));
    float lw = w - __bfloat162float(__high2bfloat16(h1));
    *(bf162*)(h + idx)     = h0;
    *(bf162*)(h + idx + 2) = h1;
    *(bf162*)(l + idx)     = __floats2bfloat162_rn(lx, ly);
    *(bf162*)(l + idx + 2) = __floats2bfloat162_rn(lz, lw);
}

// ---------------- weight split kernel ----------------
__global__ void split_kernel(const float* __restrict__ x,
                             bf16* __restrict__ h, bf16* __restrict__ l, int n4) {
    int i = blockIdx.x * blockDim.x + threadIdx.x;
    if (i >= n4) return;
    float4 v = ((const float4*)x)[i];
    split_store4(h, l, (size_t)i * 4, v.x, v.y, v.z, v.w);
}

// ---------------- 3xBF16 GEMM core (ldmatrix fragment loads) ----------------
// CTA tile 64x128, 256 threads (8 warps), warp tile 32x32, 2 CTAs/SM.
#define RPAD 20                                   // uints per 32-elem row (16 data + 4 pad)
#define ATILE_U (64 * RPAD)                       // 1280
#define BTILE_U (128 * RPAD)                      // 2560
#define STAGE_U (2 * ATILE_U + 2 * BTILE_U)       // 7680 uints = 30720 B
#define GEMM_DSMEM (2 * STAGE_U * 4)              // 61440 B

__device__ __forceinline__ void gemm_tile(float* sm,
                                          const bf16* __restrict__ Ah, const bf16* __restrict__ Al,
                                          const bf16* __restrict__ Bh, const bf16* __restrict__ Bl,
                                          const float* __restrict__ res, float* __restrict__ C,
                                          int N, int K, int bm, int bn) {
    const uint32_t smem_base = smem_u32(sm);
    const int tid  = threadIdx.x;
    const int wid  = tid >> 5;
    const int lane = tid & 31;
    const int wm   = wid >> 2;           // 0..1 -> 32-row band
    const int wn   = wid & 3;            // 0..3 -> 32-col band
    const int gid  = lane >> 2;          // 0..7
    const int tig  = lane & 3;           // 0..3
    const int KC   = K >> 5;
    const int lrow = tid >> 2;           // 0..63
    const int lch  = tid & 3;            // 0..3

    // ldmatrix lane-address components
    const int sub  = lane >> 3;          // 0..3 (8x8 submatrix id)
    const int r8   = lane & 7;
    const int arow = ((sub & 1) << 3) + r8;      // A: m0/m2 rows, m1/m3 rows+8
    const int akof = (sub >> 1) << 4;            // A: +16B for k+8 halves
    const int brow = ((sub >> 1) << 3) + r8;     // B: m0/m1 n rows, m2/m3 n+8
    const int bkof = (sub & 1) << 4;             // B: +16B for k+8 halves

    // per-lane ldmatrix base addresses (buffer 0, ks=0)
    uint32_t aaddr[2][2], baddr[2][2];           // [mt][hi/lo], [ntpair][hi/lo]
    #pragma unroll
    for (int mt = 0; mt < 2; mt++) {
        uint32_t base = smem_base + (uint32_t)((wm * 32 + mt * 16 + arow) * RPAD) * 4 + akof;
        aaddr[mt][0] = base;
        aaddr[mt][1] = base + ATILE_U * 4;
    }
    #pragma unroll
    for (int np = 0; np < 2; np++) {
        uint32_t base = smem_base + (uint32_t)(2 * ATILE_U + (wn * 32 + np * 16 + brow) * RPAD) * 4 + bkof;
        baddr[np][0] = base;
        baddr[np][1] = base + BTILE_U * 4;
    }

    float acc[2][4][4];
    #pragma unroll
    for (int i = 0; i < 2; i++)
        #pragma unroll
        for (int j = 0; j < 4; j++)
            #pragma unroll
            for (int k = 0; k < 4; k++) acc[i][j][k] = 0.f;

    auto issue_load = [&](int c, int buf) {
        const int k0 = c << 5;
        uint32_t st = smem_base + buf * (STAGE_U * 4);
        cp_async16(st + (lrow * RPAD + lch * 4) * 4,
                   Ah + (size_t)(bm + lrow) * K + k0 + lch * 8);
        cp_async16(st + (ATILE_U + lrow * RPAD + lch * 4) * 4,
                   Al + (size_t)(bm + lrow) * K + k0 + lch * 8);
        #pragma unroll
        for (int it = 0; it < 2; it++) {
            int br = it * 64 + lrow;
            cp_async16(st + (2 * ATILE_U + br * RPAD + lch * 4) * 4,
                       Bh + (size_t)(bn + br) * K + k0 + lch * 8);
            cp_async16(st + (2 * ATILE_U + BTILE_U + br * RPAD + lch * 4) * 4,
                       Bl + (size_t)(bn + br) * K + k0 + lch * 8);
        }
        CP_ASYNC_COMMIT();
    };

    issue_load(0, 0);

    for (int c = 0; c < KC; c++) {
        const int buf = c & 1;
        CP_ASYNC_WAIT0();
        __syncthreads();
        if (c + 1 < KC) issue_load(c + 1, buf ^ 1);

        const uint32_t boff = (uint32_t)buf * (STAGE_U * 4);

        #pragma unroll
        for (int ks = 0; ks < 2; ks++) {
            const uint32_t koff = boff + ks * 32;   // ks*8 uints = 32 B
            uint32_t ahf[2][4], alf[2][4], bhf[4][2], blf[4][2];
            #pragma unroll
            for (int mt = 0; mt < 2; mt++) {
                LDMX4(ahf[mt][0], ahf[mt][1], ahf[mt][2], ahf[mt][3], aaddr[mt][0] + koff);
                LDMX4(alf[mt][0], alf[mt][1], alf[mt][2], alf[mt][3], aaddr[mt][1] + koff);
            }
            #pragma unroll
            for (int np = 0; np < 2; np++) {
                LDMX4(bhf[2*np][0], bhf[2*np][1], bhf[2*np+1][0], bhf[2*np+1][1],
                      baddr[np][0] + koff);
                LDMX4(blf[2*np][0], blf[2*np][1], blf[2*np+1][0], blf[2*np+1][1],
                      baddr[np][1] + koff);
            }
            #pragma unroll
            for (int mt = 0; mt < 2; mt++)
                #pragma unroll
                for (int nt = 0; nt < 4; nt++) {
                    mma_bf16(acc[mt][nt][0], acc[mt][nt][1],
                             acc[mt][nt][2], acc[mt][nt][3],
                             ahf[mt][0], ahf[mt][1], ahf[mt][2], ahf[mt][3],
                             blf[nt][0], blf[nt][1]);
                    mma_bf16(acc[mt][nt][0], acc[mt][nt][1],
                             acc[mt][nt][2], acc[mt][nt][3],
                             alf[mt][0], alf[mt][1], alf[mt][2], alf[mt][3],
                             bhf[nt][0], bhf[nt][1]);
                    mma_bf16(acc[mt][nt][0], acc[mt][nt][1],
                             acc[mt][nt][2], acc[mt][nt][3],
                             ahf[mt][0], ahf[mt][1], ahf[mt][2], ahf[mt][3],
                             bhf[nt][0], bhf[nt][1]);
                }
        }
        __syncthreads();
    }

    #pragma unroll
    for (int mt = 0; mt < 2; mt++) {
        int r0 = bm + wm * 32 + mt * 16 + gid;
        #pragma unroll
        for (int nt = 0; nt < 4; nt++) {
            int col = bn + wn * 32 + nt * 8 + tig * 2;
            size_t o0 = (size_t)r0 * N + col;
            size_t o1 = (size_t)(r0 + 8) * N + col;
            float2 v0 = make_float2(acc[mt][nt][0], acc[mt][nt][1]);
            float2 v1 = make_float2(acc[mt][nt][2], acc[mt][nt][3]);
            if (res) {
                float2 r0v = *(const float2*)(res + o0);
                float2 r1v = *(const float2*)(res + o1);
                v0.x += r0v.x; v0.y += r0v.y;
                v1.x += r1v.x; v1.y += r1v.y;
            }
            *(float2*)(C + o0) = v0;
            *(float2*)(C + o1) = v1;
        }
    }
}

// ---- generic GEMM (o-proj, down-proj) ----
__global__ void __launch_bounds__(256, 2)
gemm_mma_kernel(const bf16* __restrict__ Ah, const bf16* __restrict__ Al,
                const bf16* __restrict__ Bh, const bf16* __restrict__ Bl,
                const float* __restrict__ res, float* __restrict__ C,
                int N, int K) {
    extern __shared__ float sm[];
    gemm_tile(sm, Ah, Al, Bh, Bl, res, C, N, K, blockIdx.y * 64, blockIdx.x * 128);
}

// ---- fused QKV projection ----
__global__ void __launch_bounds__(256, 2)
gemm_qkv_kernel(const bf16* __restrict__ Ah, const bf16* __restrict__ Al,
                float* __restrict__ q, float* __restrict__ k, float* __restrict__ v) {
    extern __shared__ float sm[];
    const int ct = blockIdx.x;
    const bf16 *Bh, *Bl; float* C; int N, bn;
    if (ct < 16)      { Bh = s_wq_h; Bl = s_wq_l; C = q; N = NH  * HD; bn = ct * 128; }
    else if (ct < 20) { Bh = s_wk_h; Bl = s_wk_l; C = k; N = NKV * HD; bn = (ct - 16) * 128; }
    else              { Bh = s_wv_h; Bl = s_wv_l; C = v; N = NKV * HD; bn = (ct - 20) * 128; }
    gemm_tile(sm, Ah, Al, Bh, Bl, nullptr, C, N, H, blockIdx.y * 64, bn);
}

// ---- fused gate/up ----
__global__ void __launch_bounds__(256, 2)
gemm_gu_kernel(const bf16* __restrict__ Ah, const bf16* __restrict__ Al,
               float* __restrict__ gg, float* __restrict__ uu) {
    extern __shared__ float sm[];
    const int ct = blockIdx.x;
    const bf16* Bh = (ct < 64) ? s_wg_h : s_wu_h;
    const bf16* Bl = (ct < 64) ? s_wg_l : s_wu_l;
    float* C       = (ct < 64) ? gg : uu;
    const int bn   = (ct & 63) * 128;
    gemm_tile(sm, Ah, Al, Bh, Bl, nullptr, C, IM, H, blockIdx.y * 64, bn);
}

// ---------------- RMSNorm with split output ----------------
__global__ void rmsnorm_split_kernel(const float* __restrict__ x,
                                     const float* __restrict__ w,
                                     bf16* __restrict__ oh, bf16* __restrict__ ol) {
    int row = blockIdx.x;
    const float* xr = x + (size_t)row * H;
    float ss = 0.f;
    for (int i = threadIdx.x; i < H / 4; i += blockDim.x) {
        float4 v = ((const float4*)xr)[i];
        ss += v.x * v.x + v.y * v.y + v.z * v.z + v.w * v.w;
    }
    __shared__ float red[32];
    #pragma unroll
    for (int o = 16; o; o >>= 1) ss += __shfl_xor_sync(0xffffffffu, ss, o);
    if ((threadIdx.x & 31) == 0) red[threadIdx.x >> 5] = ss;
    __syncthreads();
    if (threadIdx.x < 32) {
        float v = (threadIdx.x < (blockDim.x >> 5)) ? red[threadIdx.x] : 0.f;
        #pragma unroll
        for (int o = 16; o; o >>= 1) v += __shfl_xor_sync(0xffffffffu, v, o);
        if (threadIdx.x == 0) red[0] = v;
    }
    __syncthreads();
    float r = rsqrtf(red[0] / (float)H + 1e-6f);
    for (int i = threadIdx.x; i < H / 4; i += blockDim.x) {
        float4 v = ((const float4*)xr)[i];
        float4 wv = ((const float4*)w)[i];
        split_store4(oh, ol, (size_t)row * H + 4 * i,
                     v.x * r * wv.x, v.y * r * wv.y, v.z * r * wv.z, v.w * r * wv.w);
    }
}

// ---------------- RoPE ----------------
__global__ void rope_q_kernel(float* __restrict__ q,
                              const float* __restrict__ cosp,
                              const float* __restrict__ sinp,
                              const int* __restrict__ pos) {
    int idx = blockIdx.x * blockDim.x + threadIdx.x;
    int d2 = idx & 31;
    int h  = (idx >> 5) & (NH - 1);
    int bt = idx >> 10;
    int p  = pos[bt];
    float c = cosp[p * 32 + d2], s = sinp[p * 32 + d2];
    size_t base = (size_t)bt * (NH * HD) + h * HD + 2 * d2;
    float x1 = q[base], x2 = q[base + 1];
    q[base]     = x1 * c - x2 * s;
    q[base + 1] = x1 * s + x2 * c;
}

__global__ void rope_kv_kernel(float* __restrict__ k, const float* __restrict__ v,
                               const float* __restrict__ cosp,
                               const float* __restrict__ sinp,
                               const int* __restrict__ pos,
                               float* __restrict__ outk, float* __restrict__ outv) {
    int idx = blockIdx.x * blockDim.x + threadIdx.x;
    int d2 = idx & 31;
    int h  = (idx >> 5) & (NKV - 1);
    int bt = idx >> 8;
    int t  = bt & (T - 1);
    int b  = bt >> 10;
    int p  = pos[bt];
    float c = cosp[p * 32 + d2], s = sinp[p * 32 + d2];
    size_t base = (size_t)bt * (NKV * HD) + h * HD + 2 * d2;
    float x1 = k[base], x2 = k[base + 1];
    float r1 = x1 * c - x2 * s;
    float r2 = x1 * s + x2 * c;
    k[base] = r1; k[base + 1] = r2;
    size_t ob = (((size_t)(b * NKV + h)) * T + t) * HD + 2 * d2;
    outk[ob] = r1;       outk[ob + 1] = r2;
    outv[ob] = v[base];  outv[ob + 1] = v[base + 1];
}

// ---------------- Flash attention (64x64 tiles, fp32, split output) --------
__global__ void __launch_bounds__(256)
attn_kernel(const float* __restrict__ Q, const float* __restrict__ Kg,
            const float* __restrict__ Vg,
            bf16* __restrict__ Oh, bf16* __restrict__ Ol) {
    __shared__ __align__(16) float QsT[64][64];
    __shared__ __align__(16) float KsT[64][64];
    __shared__ __align__(16) float Vs [64][64];
    float (*Ps)[64] = KsT;

    const int qt = blockIdx.x, h = blockIdx.y, b = blockIdx.z;
    const int kvh = h >> 2;
    const int tid = threadIdx.x;
    const int rg = tid >> 4, cg = tid & 15;
    const int m0 = rg * 4, n0 = cg * 4;

    {
        const int m = tid >> 2;
        const int d0 = (tid & 3) * 16;
        const float* qp = Q + ((size_t)(b * T + qt * 64 + m)) * (NH * HD) + h * HD + d0;
        #pragma unroll
        for (int i = 0; i < 16; i++) QsT[d0 + i][m] = qp[i];
    }

    float o_acc[4][4] = {};
    float row_max[4] = {-1e30f, -1e30f, -1e30f, -1e30f};
    float row_sum[4] = {0.f, 0.f, 0.f, 0.f};

    for (int kt = 0; kt <= qt; kt++) {
        __syncthreads();
        {
            const int n = tid >> 2;
            const int d0 = (tid & 3) * 16;
            const float* kp = Kg + ((size_t)(b * T + kt * 64 + n)) * (NKV * HD) + kvh * HD + d0;
            const float* vp = Vg + ((size_t)(b * T + kt * 64 + n)) * (NKV * HD) + kvh * HD + d0;
            #pragma unroll
            for (int i = 0; i < 16; i++) KsT[d0 + i][n] = kp[i];
            #pragma unroll
            for (int i = 0; i < 16; i += 4)
                *(float4*)&Vs[n][d0 + i] = *(const float4*)(vp + i);
        }
        __syncthreads();

        float s[4][4] = {};
        #pragma unroll 16
        for (int d = 0; d < 64; d++) {
            float4 av = *(const float4*)&QsT[d][m0];
            float4 bv = *(const float4*)&KsT[d][n0];
            float aa[4] = {av.x, av.y, av.z, av.w};
            float bb[4] = {bv.x, bv.y, bv.z, bv.w};
            #pragma unroll
            for (int i = 0; i < 4; i++)
                #pragma unroll
                for (int j = 0; j < 4; j++)
                    s[i][j] = fmaf(aa[i], bb[j], s[i][j]);
        }

        const float scale = 0.125f;
        if (kt == qt) {
            #pragma unroll
            for (int i = 0; i < 4; i++)
                #pragma unroll
                for (int j = 0; j < 4; j++)
                    s[i][j] = (n0 + j <= m0 + i) ? s[i][j] * scale : -1e30f;
        } else {
            #pragma unroll
            for (int i = 0; i < 4; i++)
                #pragma unroll
                for (int j = 0; j < 4; j++)
                    s[i][j] *= scale;
        }

        float p[4][4];
        #pragma unroll
        for (int i = 0; i < 4; i++) {
            float mx = fmaxf(fmaxf(s[i][0], s[i][1]), fmaxf(s[i][2], s[i][3]));
            #pragma unroll
            for (int o = 1; o < 16; o <<= 1)
                mx = fmaxf(mx, __shfl_xor_sync(0xffffffffu, mx, o));
            float nm = fmaxf(row_max[i], mx);
            float alpha = __expf(row_max[i] - nm);
            row_max[i] = nm;
            float rs = 0.f;
            #pragma unroll
            for (int j = 0; j < 4; j++) { p[i][j] = __expf(s[i][j] - nm); rs += p[i][j]; }
            #pragma unroll
            for (int o = 1; o < 16; o <<= 1)
                rs += __shfl_xor_sync(0xffffffffu, rs, o);
            row_sum[i] = row_sum[i] * alpha + rs;
            #pragma unroll
            for (int j = 0; j < 4; j++) o_acc[i][j] *= alpha;
        }

        __syncthreads();
        #pragma unroll
        for (int i = 0; i < 4; i++)
            #pragma unroll
            for (int j = 0; j < 4; j++)
                Ps[m0 + i][n0 + j] = p[i][j];
        __syncthreads();

        #pragma unroll 8
        for (int n = 0; n < 64; n++) {
            float4 vv = *(const float4*)&Vs[n][n0];
            float vb[4] = {vv.x, vv.y, vv.z, vv.w};
            #pragma unroll
            for (int i = 0; i < 4; i++) {
                float pv = Ps[m0 + i][n];
                #pragma unroll
                for (int j = 0; j < 4; j++)
                    o_acc[i][j] = fmaf(pv, vb[j], o_acc[i][j]);
            }
        }
    }

    #pragma unroll
    for (int i = 0; i < 4; i++) {
        float inv = 1.f / row_sum[i];
        int t = qt * 64 + m0 + i;
        size_t off = ((size_t)(b * T + t)) * (NH * HD) + h * HD + n0;
        split_store4(Oh, Ol, off,
                     o_acc[i][0] * inv, o_acc[i][1] * inv,
                     o_acc[i][2] * inv, o_acc[i][3] * inv);
    }
}

// ---------------- SwiGLU elementwise with split output ----------------
__global__ void silu_mul_split_kernel(const float* __restrict__ g,
                                      const float* __restrict__ u,
                                      bf16* __restrict__ oh, bf16* __restrict__ ol) {
    size_t i = (size_t)blockIdx.x * blockDim.x + threadIdx.x;
    float4 gv = ((const float4*)g)[i];
    float4 uv = ((const float4*)u)[i];
    float rx = gv.x / (1.f + __expf(-gv.x)) * uv.x;
    float ry = gv.y / (1.f + __expf(-gv.y)) * uv.y;
    float rz = gv.z / (1.f + __expf(-gv.z)) * uv.z;
    float rw = gv.w / (1.f + __expf(-gv.w)) * uv.w;
    split_store4(oh, ol, i * 4, rx, ry, rz, rw);
}

// ---------------- launch ----------------
extern "C" void kernel_launch(void* const* d_in, const int* in_sizes, int n_in,
                              void* d_out, int out_size) {
    const float* hs   = (const float*)d_in[0];
    const float* cosp = (const float*)d_in[1];
    const float* sinp = (const float*)d_in[2];
    const int*   pos  = (const int*)  d_in[3];
    const float* n1w  = (const float*)d_in[5];
    const float* wq   = (const float*)d_in[6];
    const float* wk   = (const float*)d_in[7];
    const float* wv   = (const float*)d_in[8];
    const float* wo   = (const float*)d_in[9];
    const float* n2w  = (const float*)d_in[10];
    const float* wg   = (const float*)d_in[11];
    const float* wu   = (const float*)d_in[12];
    const float* wd   = (const float*)d_in[13];

    float *q, *k, *v, *h2, *gg, *uu;
    cudaGetSymbolAddress((void**)&q,  g_q);
    cudaGetSymbolAddress((void**)&k,  g_k);
    cudaGetSymbolAddress((void**)&v,  g_v);
    cudaGetSymbolAddress((void**)&h2, g_h2);
    cudaGetSymbolAddress((void**)&gg, g_gg);
    cudaGetSymbolAddress((void**)&uu, g_uu);

    bf16 *wqh,*wql,*wkh,*wkl,*wvh,*wvl,*woh,*wol,*wgh,*wgl,*wuh,*wul,*wdh,*wdl;
    bf16 *xnh,*xnl,*ath,*atl,*xn2h,*xn2l,*gh,*gl;
    cudaGetSymbolAddress((void**)&wqh, s_wq_h);  cudaGetSymbolAddress((void**)&wql, s_wq_l);
    cudaGetSymbolAddress((void**)&wkh, s_wk_h);  cudaGetSymbolAddress((void**)&wkl, s_wk_l);
    cudaGetSymbolAddress((void**)&wvh, s_wv_h);  cudaGetSymbolAddress((void**)&wvl, s_wv_l);
    cudaGetSymbolAddress((void**)&woh, s_wo_h);  cudaGetSymbolAddress((void**)&wol, s_wo_l);
    cudaGetSymbolAddress((void**)&wgh, s_wg_h);  cudaGetSymbolAddress((void**)&wgl, s_wg_l);
    cudaGetSymbolAddress((void**)&wuh, s_wu_h);  cudaGetSymbolAddress((void**)&wul, s_wu_l);
    cudaGetSymbolAddress((void**)&wdh, s_wd_h);  cudaGetSymbolAddress((void**)&wdl, s_wd_l);
    cudaGetSymbolAddress((void**)&xnh, s_xn_h);  cudaGetSymbolAddress((void**)&xnl, s_xn_l);
    cudaGetSymbolAddress((void**)&ath, s_at_h);  cudaGetSymbolAddress((void**)&atl, s_at_l);
    cudaGetSymbolAddress((void**)&xn2h, s_xn2_h);cudaGetSymbolAddress((void**)&xn2l, s_xn2_l);
    cudaGetSymbolAddress((void**)&gh,  s_g_h);   cudaGetSymbolAddress((void**)&gl,  s_g_l);

    float* out_x = (float*)d_out;
    float* out_k = out_x + (size_t)M * H;
    float* out_v = out_k + (size_t)B * NKV * T * HD;

    cudaFuncSetAttribute(gemm_mma_kernel,
                         cudaFuncAttributeMaxDynamicSharedMemorySize, GEMM_DSMEM);
    cudaFuncSetAttribute(gemm_qkv_kernel,
                         cudaFuncAttributeMaxDynamicSharedMemorySize, GEMM_DSMEM);
    cudaFuncSetAttribute(gemm_gu_kernel,
                         cudaFuncAttributeMaxDynamicSharedMemorySize, GEMM_DSMEM);

    // 0. split weights (hi/lo bf16)
    split_kernel<<<(NH*HD*H/4 + 255)/256, 256>>>(wq, wqh, wql, NH*HD*H/4);
    split_kernel<<<(NKV*HD*H/4 + 255)/256, 256>>>(wk, wkh, wkl, NKV*HD*H/4);
    split_kernel<<<(NKV*HD*H/4 + 255)/256, 256>>>(wv, wvh, wvl, NKV*HD*H/4);
    split_kernel<<<(H*NH*HD/4 + 255)/256, 256>>>(wo, woh, wol, H*NH*HD/4);
    split_kernel<<<(IM*H/4 + 255)/256, 256>>>(wg, wgh, wgl, IM*H/4);
    split_kernel<<<(IM*H/4 + 255)/256, 256>>>(wu, wuh, wul, IM*H/4);
    split_kernel<<<(H*IM/4 + 255)/256, 256>>>(wd, wdh, wdl, H*IM/4);

    // 1. RMSNorm 1 (split output)
    rmsnorm_split_kernel<<<M, 256>>>(hs, n1w, xnh, xnl);
    // 2. fused Q/K/V projections
    gemm_qkv_kernel<<<dim3(24, M / 64), 256, GEMM_DSMEM>>>(xnh, xnl, q, k, v);
    // 3. RoPE + KV-cache writeout
    rope_q_kernel <<<(B * T * NH  * (HD / 2)) / 256, 256>>>(q, cosp, sinp, pos);
    rope_kv_kernel<<<(B * T * NKV * (HD / 2)) / 256, 256>>>(k, v, cosp, sinp, pos,
                                                            out_k, out_v);
    // 4. Attention (split output)
    attn_kernel<<<dim3(T / 64, NH, B), 256>>>(q, k, v, ath, atl);
    // 5. O-projection + residual
    gemm_mma_kernel<<<dim3(H / 128, M / 64), 256, GEMM_DSMEM>>>(ath, atl, woh, wol,
                                                                hs, h2, H, NH * HD);
    // 6. RMSNorm 2 (split output)
    rmsnorm_split_kernel<<<M, 256>>>(h2, n2w, xn2h, xn2l);
    // 7. fused MLP gate/up
    gemm_gu_kernel<<<dim3(128, M / 64), 256, GEMM_DSMEM>>>(xn2h, xn2l, gg, uu);
    // 8. SwiGLU (split output)
    silu_mul_split_kernel<<<((size_t)M * IM / 4) / 256, 256>>>(gg, uu, gh, gl);
    // 9. Down projection + residual -> x output
    gemm_mma_kernel<<<dim3(H / 128, M / 64), 256, GEMM_DSMEM>>>(gh, gl, wdh, wdl,
                                                                h2, out_x, H, IM);
}

// round 9
// speedup vs baseline: 2.3867x; 1.1208x over previous
#include <cuda_runtime.h>
#include <cuda_bf16.h>
#include <math.h>
#include <stdint.h>

#define B   2
#define T   1024
#define H   2048
#define NH  32
#define NKV 8
#define HD  64
#define IM  8192
#define M   (B*T)

typedef __nv_bfloat16  bf16;
typedef __nv_bfloat162 bf162;

// ---------------- scratch (device globals; no allocation) ----------------
__device__ __align__(16) float g_q  [M * NH * HD];
__device__ __align__(16) float g_k  [M * NKV * HD];
__device__ __align__(16) float g_v  [M * NKV * HD];
__device__ __align__(16) float g_h2 [M * H];
__device__ __align__(16) float g_gg [(size_t)M * IM];
__device__ __align__(16) float g_uu [(size_t)M * IM];
// bf16 hi/lo split weights
__device__ __align__(16) bf16 s_wq_h[NH*HD*H],  s_wq_l[NH*HD*H];
__device__ __align__(16) bf16 s_wk_h[NKV*HD*H], s_wk_l[NKV*HD*H];
__device__ __align__(16) bf16 s_wv_h[NKV*HD*H], s_wv_l[NKV*HD*H];
__device__ __align__(16) bf16 s_wo_h[H*NH*HD],  s_wo_l[H*NH*HD];
__device__ __align__(16) bf16 s_wg_h[(size_t)IM*H], s_wg_l[(size_t)IM*H];
__device__ __align__(16) bf16 s_wu_h[(size_t)IM*H], s_wu_l[(size_t)IM*H];
__device__ __align__(16) bf16 s_wd_h[(size_t)H*IM], s_wd_l[(size_t)H*IM];
// bf16 hi/lo split activations
__device__ __align__(16) bf16 s_xn_h [M*H],        s_xn_l [M*H];
__device__ __align__(16) bf16 s_at_h [M*NH*HD],    s_at_l [M*NH*HD];
__device__ __align__(16) bf16 s_xn2_h[M*H],        s_xn2_l[M*H];
__device__ __align__(16) bf16 s_g_h  [(size_t)M*IM], s_g_l[(size_t)M*IM];
// bf16 hi/lo split q/k/v for attention (head-major; v transposed)
__device__ __align__(16) bf16 s_q_h [M*NH*HD],  s_q_l [M*NH*HD];
__device__ __align__(16) bf16 s_k_h [M*NKV*HD], s_k_l [M*NKV*HD];
__device__ __align__(16) bf16 s_vt_h[M*NKV*HD], s_vt_l[M*NKV*HD];

// ---------------- helpers ----------------
__device__ __forceinline__ uint32_t smem_u32(const void* p) {
    uint32_t a;
    asm("{ .reg .u64 t; cvta.to.shared.u64 t, %1; cvt.u32.u64 %0, t; }"
        : "=r"(a) : "l"(p));
    return a;
}
__device__ __forceinline__ void cp_async16(uint32_t dst, const void* src) {
    asm volatile("cp.async.cg.shared.global [%0], [%1], 16;"
                 :: "r"(dst), "l"(src));
}
#define CP_ASYNC_COMMIT() asm volatile("cp.async.commit_group;" ::: "memory")
#define CP_ASYNC_WAIT0()  asm volatile("cp.async.wait_group 0;" ::: "memory")

#define LDMX4(r0, r1, r2, r3, addr) \
    asm volatile("ldmatrix.sync.aligned.m8n8.x4.shared.b16 {%0,%1,%2,%3}, [%4];" \
        : "=r"(r0), "=r"(r1), "=r"(r2), "=r"(r3) : "r"(addr))

__device__ __forceinline__ void mma_bf16(float& c0, float& c1, float& c2, float& c3,
                                         uint32_t a0, uint32_t a1, uint32_t a2, uint32_t a3,
                                         uint32_t b0, uint32_t b1) {
    asm volatile(
        "mma.sync.aligned.m16n8k16.row.col.f32.bf16.bf16.f32 "
        "{%0,%1,%2,%3}, {%4,%5,%6,%7}, {%8,%9}, {%0,%1,%2,%3};"
        : "+f"(c0), "+f"(c1), "+f"(c2), "+f"(c3)
        : "r"(a0), "r"(a1), "r"(a2), "r"(a3), "r"(b0), "r"(b1));
}

// split-store 4 consecutive fp32 -> hi/lo bf16 arrays
__device__ __forceinline__ void split_store4(bf16* __restrict__ h, bf16* __restrict__ l,
                                             size_t idx, float x, float y, float z, float w) {
    bf162 h0 = __floats2bfloat162_rn(x, y);
    bf162 h1 = __floats2bfloat162_rn(z, w);
    float lx = x - __bfloat162float(__low2bfloat16(h0));
    float ly = y - __bfloat162float(__high2bfloat16(h0));
    float lz = z - __bfloat162float(__low2bfloat16(h1));
    float lw = w - __bfloat162float(__high2bfloat16(h1));
    *(bf162*)(h + idx)     = h0;
    *(bf162*)(h + idx + 2) = h1;
    *(bf162*)(l + idx)     = __floats2bfloat162_rn(lx, ly);
    *(bf162*)(l + idx + 2) = __floats2bfloat162_rn(lz, lw);
}
// split-store a pair
__device__ __forceinline__ void split_store2(bf16* __restrict__ h, bf16* __restrict__ l,
                                             size_t idx, float x, float y) {
    bf162 h0 = __floats2bfloat162_rn(x, y);
    float lx = x - __bfloat162float(__low2bfloat16(h0));
    float ly = y - __bfloat162float(__high2bfloat16(h0));
    *(bf162*)(h + idx) = h0;
    *(bf162*)(l + idx) = __floats2bfloat162_rn(lx, ly);
}
// pack two fp32 to bf16x2 hi + bf16x2 residual
__device__ __forceinline__ void pack_split2(float x, float y, uint32_t& hi, uint32_t& lo) {
    bf162 h0 = __floats2bfloat162_rn(x, y);
    float lx = x - __bfloat162float(__low2bfloat16(h0));
    float ly = y - __bfloat162float(__high2bfloat16(h0));
    bf162 l0 = __floats2bfloat162_rn(lx, ly);
    hi = *(uint32_t*)&h0;
    lo = *(uint32_t*)&l0;
}

// ---------------- weight split kernel ----------------
__global__ void split_kernel(const float* __restrict__ x,
                             bf16* __restrict__ h, bf16* __restrict__ l, int n4) {
    int i = blockIdx.x * blockDim.x + threadIdx.x;
    if (i >= n4) return;
    float4 v = ((const float4*)x)[i];
    split_store4(h, l, (size_t)i * 4, v.x, v.y, v.z, v.w);
}

// ---------------- 3xBF16 GEMM core (ldmatrix fragment loads) ----------------
#define RPAD 20
#define ATILE_U (64 * RPAD)
#define BTILE_U (128 * RPAD)
#define STAGE_U (2 * ATILE_U + 2 * BTILE_U)
#define GEMM_DSMEM (2 * STAGE_U * 4)

__device__ __forceinline__ void gemm_tile(float* sm,
                                          const bf16* __restrict__ Ah, const bf16* __restrict__ Al,
                                          const bf16* __restrict__ Bh, const bf16* __restrict__ Bl,
                                          const float* __restrict__ res, float* __restrict__ C,
                                          int N, int K, int bm, int bn) {
    const uint32_t smem_base = smem_u32(sm);
    const int tid  = threadIdx.x;
    const int wid  = tid >> 5;
    const int lane = tid & 31;
    const int wm   = wid >> 2;
    const int wn   = wid & 3;
    const int gid  = lane >> 2;
    const int tig  = lane & 3;
    const int KC   = K >> 5;
    const int lrow = tid >> 2;
    const int lch  = tid & 3;

    const int sub  = lane >> 3;
    const int r8   = lane & 7;
    const int arow = ((sub & 1) << 3) + r8;
    const int akof = (sub >> 1) << 4;
    const int brow = ((sub >> 1) << 3) + r8;
    const int bkof = (sub & 1) << 4;

    uint32_t aaddr[2][2], baddr[2][2];
    #pragma unroll
    for (int mt = 0; mt < 2; mt++) {
        uint32_t base = smem_base + (uint32_t)((wm * 32 + mt * 16 + arow) * RPAD) * 4 + akof;
        aaddr[mt][0] = base;
        aaddr[mt][1] = base + ATILE_U * 4;
    }
    #pragma unroll
    for (int np = 0; np < 2; np++) {
        uint32_t base = smem_base + (uint32_t)(2 * ATILE_U + (wn * 32 + np * 16 + brow) * RPAD) * 4 + bkof;
        baddr[np][0] = base;
        baddr[np][1] = base + BTILE_U * 4;
    }

    float acc[2][4][4];
    #pragma unroll
    for (int i = 0; i < 2; i++)
        #pragma unroll
        for (int j = 0; j < 4; j++)
            #pragma unroll
            for (int k = 0; k < 4; k++) acc[i][j][k] = 0.f;

    auto issue_load = [&](int c, int buf) {
        const int k0 = c << 5;
        uint32_t st = smem_base + buf * (STAGE_U * 4);
        cp_async16(st + (lrow * RPAD + lch * 4) * 4,
                   Ah + (size_t)(bm + lrow) * K + k0 + lch * 8);
        cp_async16(st + (ATILE_U + lrow * RPAD + lch * 4) * 4,
                   Al + (size_t)(bm + lrow) * K + k0 + lch * 8);
        #pragma unroll
        for (int it = 0; it < 2; it++) {
            int br = it * 64 + lrow;
            cp_async16(st + (2 * ATILE_U + br * RPAD + lch * 4) * 4,
                       Bh + (size_t)(bn + br) * K + k0 + lch * 8);
            cp_async16(st + (2 * ATILE_U + BTILE_U + br * RPAD + lch * 4) * 4,
                       Bl + (size_t)(bn + br) * K + k0 + lch * 8);
        }
        CP_ASYNC_COMMIT();
    };

    issue_load(0, 0);

    for (int c = 0; c < KC; c++) {
        const int buf = c & 1;
        CP_ASYNC_WAIT0();
        __syncthreads();
        if (c + 1 < KC) issue_load(c + 1, buf ^ 1);

        const uint32_t boff = (uint32_t)buf * (STAGE_U * 4);

        #pragma unroll
        for (int ks = 0; ks < 2; ks++) {
            const uint32_t koff = boff + ks * 32;
            uint32_t ahf[2][4], alf[2][4], bhf[4][2], blf[4][2];
            #pragma unroll
            for (int mt = 0; mt < 2; mt++) {
                LDMX4(ahf[mt][0], ahf[mt][1], ahf[mt][2], ahf[mt][3], aaddr[mt][0] + koff);
                LDMX4(alf[mt][0], alf[mt][1], alf[mt][2], alf[mt][3], aaddr[mt][1] + koff);
            }
            #pragma unroll
            for (int np = 0; np < 2; np++) {
                LDMX4(bhf[2*np][0], bhf[2*np][1], bhf[2*np+1][0], bhf[2*np+1][1],
                      baddr[np][0] + koff);
                LDMX4(blf[2*np][0], blf[2*np][1], blf[2*np+1][0], blf[2*np+1][1],
                      baddr[np][1] + koff);
            }
            #pragma unroll
            for (int mt = 0; mt < 2; mt++)
                #pragma unroll
                for (int nt = 0; nt < 4; nt++) {
                    mma_bf16(acc[mt][nt][0], acc[mt][nt][1],
                             acc[mt][nt][2], acc[mt][nt][3],
                             ahf[mt][0], ahf[mt][1], ahf[mt][2], ahf[mt][3],
                             blf[nt][0], blf[nt][1]);
                    mma_bf16(acc[mt][nt][0], acc[mt][nt][1],
                             acc[mt][nt][2], acc[mt][nt][3],
                             alf[mt][0], alf[mt][1], alf[mt][2], alf[mt][3],
                             bhf[nt][0], bhf[nt][1]);
                    mma_bf16(acc[mt][nt][0], acc[mt][nt][1],
                             acc[mt][nt][2], acc[mt][nt][3],
                             ahf[mt][0], ahf[mt][1], ahf[mt][2], ahf[mt][3],
                             bhf[nt][0], bhf[nt][1]);
                }
        }
        __syncthreads();
    }

    #pragma unroll
    for (int mt = 0; mt < 2; mt++) {
        int r0 = bm + wm * 32 + mt * 16 + gid;
        #pragma unroll
        for (int nt = 0; nt < 4; nt++) {
            int col = bn + wn * 32 + nt * 8 + tig * 2;
            size_t o0 = (size_t)r0 * N + col;
            size_t o1 = (size_t)(r0 + 8) * N + col;
            float2 v0 = make_float2(acc[mt][nt][0], acc[mt][nt][1]);
            float2 v1 = make_float2(acc[mt][nt][2], acc[mt][nt][3]);
            if (res) {
                float2 r0v = *(const float2*)(res + o0);
                float2 r1v = *(const float2*)(res + o1);
                v0.x += r0v.x; v0.y += r0v.y;
                v1.x += r1v.x; v1.y += r1v.y;
            }
            *(float2*)(C + o0) = v0;
            *(float2*)(C + o1) = v1;
        }
    }
}

__global__ void __launch_bounds__(256, 2)
gemm_mma_kernel(const bf16* __restrict__ Ah, const bf16* __restrict__ Al,
                const bf16* __restrict__ Bh, const bf16* __restrict__ Bl,
                const float* __restrict__ res, float* __restrict__ C,
                int N, int K) {
    extern __shared__ float sm[];
    gemm_tile(sm, Ah, Al, Bh, Bl, res, C, N, K, blockIdx.y * 64, blockIdx.x * 128);
}

__global__ void __launch_bounds__(256, 2)
gemm_qkv_kernel(const bf16* __restrict__ Ah, const bf16* __restrict__ Al,
                float* __restrict__ q, float* __restrict__ k, float* __restrict__ v) {
    extern __shared__ float sm[];
    const int ct = blockIdx.x;
    const bf16 *Bh, *Bl; float* C; int N, bn;
    if (ct < 16)      { Bh = s_wq_h; Bl = s_wq_l; C = q; N = NH  * HD; bn = ct * 128; }
    else if (ct < 20) { Bh = s_wk_h; Bl = s_wk_l; C = k; N = NKV * HD; bn = (ct - 16) * 128; }
    else              { Bh = s_wv_h; Bl = s_wv_l; C = v; N = NKV * HD; bn = (ct - 20) * 128; }
    gemm_tile(sm, Ah, Al, Bh, Bl, nullptr, C, N, H, blockIdx.y * 64, bn);
}

__global__ void __launch_bounds__(256, 2)
gemm_gu_kernel(const bf16* __restrict__ Ah, const bf16* __restrict__ Al,
               float* __restrict__ gg, float* __restrict__ uu) {
    extern __shared__ float sm[];
    const int ct = blockIdx.x;
    const bf16* Bh = (ct < 64) ? s_wg_h : s_wu_h;
    const bf16* Bl = (ct < 64) ? s_wg_l : s_wu_l;
    float* C       = (ct < 64) ? gg : uu;
    const int bn   = (ct & 63) * 128;
    gemm_tile(sm, Ah, Al, Bh, Bl, nullptr, C, IM, H, blockIdx.y * 64, bn);
}

// ---------------- RMSNorm with split output ----------------
__global__ void rmsnorm_split_kernel(const float* __restrict__ x,
                                     const float* __restrict__ w,
                                     bf16* __restrict__ oh, bf16* __restrict__ ol) {
    int row = blockIdx.x;
    const float* xr = x + (size_t)row * H;
    float ss = 0.f;
    for (int i = threadIdx.x; i < H / 4; i += blockDim.x) {
        float4 v = ((const float4*)xr)[i];
        ss += v.x * v.x + v.y * v.y + v.z * v.z + v.w * v.w;
    }
    __shared__ float red[32];
    #pragma unroll
    for (int o = 16; o; o >>= 1) ss += __shfl_xor_sync(0xffffffffu, ss, o);
    if ((threadIdx.x & 31) == 0) red[threadIdx.x >> 5] = ss;
    __syncthreads();
    if (threadIdx.x < 32) {
        float v = (threadIdx.x < (blockDim.x >> 5)) ? red[threadIdx.x] : 0.f;
        #pragma unroll
        for (int o = 16; o; o >>= 1) v += __shfl_xor_sync(0xffffffffu, v, o);
        if (threadIdx.x == 0) red[0] = v;
    }
    __syncthreads();
    float r = rsqrtf(red[0] / (float)H + 1e-6f);
    for (int i = threadIdx.x; i < H / 4; i += blockDim.x) {
        float4 v = ((const float4*)xr)[i];
        float4 wv = ((const float4*)w)[i];
        split_store4(oh, ol, (size_t)row * H + 4 * i,
                     v.x * r * wv.x, v.y * r * wv.y, v.z * r * wv.z, v.w * r * wv.w);
    }
}

// ---------------- RoPE (writes bf16 hi/lo, head-major) ----------------
__global__ void rope_q_kernel(const float* __restrict__ q,
                              const float* __restrict__ cosp,
                              const float* __restrict__ sinp,
                              const int* __restrict__ pos,
                              bf16* __restrict__ qh, bf16* __restrict__ ql) {
    int idx = blockIdx.x * blockDim.x + threadIdx.x;
    int d2 = idx & 31;
    int h  = (idx >> 5) & (NH - 1);
    int bt = idx >> 10;
    int t  = bt & (T - 1);
    int b  = bt >> 10;
    int p  = pos[bt];
    float c = cosp[p * 32 + d2], s = sinp[p * 32 + d2];
    size_t base = (size_t)bt * (NH * HD) + h * HD + 2 * d2;
    float x1 = q[base], x2 = q[base + 1];
    float r1 = x1 * c - x2 * s;
    float r2 = x1 * s + x2 * c;
    size_t ob = ((size_t)(b * NH + h) * T + t) * HD + 2 * d2;
    split_store2(qh, ql, ob, r1, r2);
}

__global__ void rope_kv_kernel(const float* __restrict__ k, const float* __restrict__ v,
                               const float* __restrict__ cosp,
                               const float* __restrict__ sinp,
                               const int* __restrict__ pos,
                               float* __restrict__ outk, float* __restrict__ outv,
                               bf16* __restrict__ kh, bf16* __restrict__ kl,
                               bf16* __restrict__ vth, bf16* __restrict__ vtl) {
    int idx = blockIdx.x * blockDim.x + threadIdx.x;
    int d2 = idx & 31;
    int h  = (idx >> 5) & (NKV - 1);
    int bt = idx >> 8;
    int t  = bt & (T - 1);
    int b  = bt >> 10;
    int p  = pos[bt];
    float c = cosp[p * 32 + d2], s = sinp[p * 32 + d2];
    size_t base = (size_t)bt * (NKV * HD) + h * HD + 2 * d2;
    float x1 = k[base], x2 = k[base + 1];
    float r1 = x1 * c - x2 * s;
    float r2 = x1 * s + x2 * c;
    size_t ob = ((size_t)(b * NKV + h) * T + t) * HD + 2 * d2;
    outk[ob] = r1;       outk[ob + 1] = r2;
    split_store2(kh, kl, ob, r1, r2);
    float v1 = v[base], v2 = v[base + 1];
    outv[ob] = v1;       outv[ob + 1] = v2;
    // transposed V: [b, h, d, t]
    size_t vb = ((size_t)(b * NKV + h) * HD + 2 * d2) * T + t;
    bf16 vh1 = __float2bfloat16(v1);
    bf16 vh2 = __float2bfloat16(v2);
    vth[vb]     = vh1; vtl[vb]     = __float2bfloat16(v1 - __bfloat162float(vh1));
    vth[vb + T] = vh2; vtl[vb + T] = __float2bfloat16(v2 - __bfloat162float(vh2));
}

// ---------------- Flash attention (3xBF16 mma, 64 q rows/CTA, 4 warps) ------
#define AT_RPAD 36                         // uints per 64-bf16 row (32 + 4 pad)
#define AT_TILE_U (64 * AT_RPAD)           // 2304
#define ATTN_DSMEM (6 * AT_TILE_U * 4)     // Qh,Ql,Kh,Kl,Vh,Vl = 55296 B

__global__ void __launch_bounds__(128)
attn_kernel(const bf16* __restrict__ Qh_g, const bf16* __restrict__ Ql_g,
            const bf16* __restrict__ Kh_g, const bf16* __restrict__ Kl_g,
            const bf16* __restrict__ Vth_g, const bf16* __restrict__ Vtl_g,
            bf16* __restrict__ Oh, bf16* __restrict__ Ol) {
    extern __shared__ uint32_t smu[];
    const int qt = blockIdx.x, h = blockIdx.y, b = blockIdx.z;
    const int kvh = h >> 2;
    const int tid = threadIdx.x, wid = tid >> 5, lane = tid & 31;
    const int gid = lane >> 2, tig = lane & 3;
    const int sub = lane >> 3, r8 = lane & 7;
    const int arow = ((sub & 1) << 3) + r8;
    const int akof = (sub >> 1) << 4;
    const int brow = ((sub >> 1) << 3) + r8;
    const int bkof = (sub & 1) << 4;

    const uint32_t smem_base = smem_u32(smu);
    const uint32_t Qh_s = smem_base;
    const uint32_t Ql_s = Qh_s + AT_TILE_U * 4;
    const uint32_t Kh_s = Ql_s + AT_TILE_U * 4;
    const uint32_t Kl_s = Kh_s + AT_TILE_U * 4;
    const uint32_t Vh_s = Kl_s + AT_TILE_U * 4;
    const uint32_t Vl_s = Vh_s + AT_TILE_U * 4;

    // ---- load Q tile (64 x 64) hi/lo ----
    {
        const bf16* qh = Qh_g + ((size_t)(b * NH + h) * T + qt * 64) * HD;
        const bf16* ql = Ql_g + ((size_t)(b * NH + h) * T + qt * 64) * HD;
        #pragma unroll
        for (int it = 0; it < 4; it++) {
            int idx = tid + it * 128;        // 0..511
            int row = idx >> 3, ch = idx & 7;
            cp_async16(Qh_s + (row * AT_RPAD + ch * 4) * 4, qh + (size_t)row * HD + ch * 8);
            cp_async16(Ql_s + (row * AT_RPAD + ch * 4) * 4, ql + (size_t)row * HD + ch * 8);
        }
        CP_ASYNC_COMMIT();
        CP_ASYNC_WAIT0();
        __syncthreads();
    }
    // ---- Q fragments in registers (whole loop) ----
    uint32_t qfh[4][4], qfl[4][4];
    {
        uint32_t qa = (uint32_t)((wid * 16 + arow) * AT_RPAD) * 4 + akof;
        #pragma unroll
        for (int ks = 0; ks < 4; ks++) {
            LDMX4(qfh[ks][0], qfh[ks][1], qfh[ks][2], qfh[ks][3], Qh_s + qa + ks * 32);
            LDMX4(qfl[ks][0], qfl[ks][1], qfl[ks][2], qfl[ks][3], Ql_s + qa + ks * 32);
        }
    }

    float oacc[8][4];
    #pragma unroll
    for (int i = 0; i < 8; i++)
        #pragma unroll
        for (int j = 0; j < 4; j++) oacc[i][j] = 0.f;
    float rm0 = -1e30f, rm1 = -1e30f, rs0 = 0.f, rs1 = 0.f;

    for (int kt = 0; kt <= qt; kt++) {
        __syncthreads();
        {   // load K (64 keys x 64 d) and V^T (64 d x 64 keys), hi/lo
            const bf16* kh  = Kh_g  + ((size_t)(b * NKV + kvh) * T + kt * 64) * HD;
            const bf16* kl  = Kl_g  + ((size_t)(b * NKV + kvh) * T + kt * 64) * HD;
            const bf16* vth = Vth_g + (size_t)(b * NKV + kvh) * HD * T;
            const bf16* vtl = Vtl_g + (size_t)(b * NKV + kvh) * HD * T;
            #pragma unroll
            for (int it = 0; it < 4; it++) {
                int idx = tid + it * 128;
                int row = idx >> 3, ch = idx & 7;
                uint32_t soff = (row * AT_RPAD + ch * 4) * 4;
                cp_async16(Kh_s + soff, kh + (size_t)row * HD + ch * 8);
                cp_async16(Kl_s + soff, kl + (size_t)row * HD + ch * 8);
                cp_async16(Vh_s + soff, vth + (size_t)row * T + kt * 64 + ch * 8);
                cp_async16(Vl_s + soff, vtl + (size_t)row * T + kt * 64 + ch * 8);
            }
            CP_ASYNC_COMMIT();
            CP_ASYNC_WAIT0();
            __syncthreads();
        }

        // ---- S = Q K^T (3-term) ----
        float sacc[8][4];
        #pragma unroll
        for (int i = 0; i < 8; i++)
            #pragma unroll
            for (int j = 0; j < 4; j++) sacc[i][j] = 0.f;

        #pragma unroll
        for (int ks = 0; ks < 4; ks++) {
            uint32_t kfh[8][2], kfl[8][2];
            #pragma unroll
            for (int np = 0; np < 4; np++) {
                uint32_t ka = (uint32_t)((np * 16 + brow) * AT_RPAD) * 4 + bkof + ks * 32;
                LDMX4(kfh[2*np][0], kfh[2*np][1], kfh[2*np+1][0], kfh[2*np+1][1], Kh_s + ka);
                LDMX4(kfl[2*np][0], kfl[2*np][1], kfl[2*np+1][0], kfl[2*np+1][1], Kl_s + ka);
            }
            #pragma unroll
            for (int nt = 0; nt < 8; nt++) {
                mma_bf16(sacc[nt][0], sacc[nt][1], sacc[nt][2], sacc[nt][3],
                         qfh[ks][0], qfh[ks][1], qfh[ks][2], qfh[ks][3],
                         kfl[nt][0], kfl[nt][1]);
                mma_bf16(sacc[nt][0], sacc[nt][1], sacc[nt][2], sacc[nt][3],
                         qfl[ks][0], qfl[ks][1], qfl[ks][2], qfl[ks][3],
                         kfh[nt][0], kfh[nt][1]);
                mma_bf16(sacc[nt][0], sacc[nt][1], sacc[nt][2], sacc[nt][3],
                         qfh[ks][0], qfh[ks][1], qfh[ks][2], qfh[ks][3],
                         kfh[nt][0], kfh[nt][1]);
            }
        }

        // ---- scale + causal mask ----
        const float scale = 0.125f;
        if (kt == qt) {
            #pragma unroll
            for (int nt = 0; nt < 8; nt++)
                #pragma unroll
                for (int c = 0; c < 4; c++) {
                    int col = 8 * nt + 2 * tig + (c & 1);
                    int row = wid * 16 + gid + ((c >> 1) << 3);
                    sacc[nt][c] = (col <= row) ? sacc[nt][c] * scale : -1e30f;
                }
        } else {
            #pragma unroll
            for (int nt = 0; nt < 8; nt++)
                #pragma unroll
                for (int c = 0; c < 4; c++) sacc[nt][c] *= scale;
        }

        // ---- online softmax (rows: c0,c1 -> gid; c2,c3 -> gid+8) ----
        float mx0 = -1e30f, mx1 = -1e30f;
        #pragma unroll
        for (int nt = 0; nt < 8; nt++) {
            mx0 = fmaxf(mx0, fmaxf(sacc[nt][0], sacc[nt][1]));
            mx1 = fmaxf(mx1, fmaxf(sacc[nt][2], sacc[nt][3]));
        }
        mx0 = fmaxf(mx0, __shfl_xor_sync(0xffffffffu, mx0, 1));
        mx0 = fmaxf(mx0, __shfl_xor_sync(0xffffffffu, mx0, 2));
        mx1 = fmaxf(mx1, __shfl_xor_sync(0xffffffffu, mx1, 1));
        mx1 = fmaxf(mx1, __shfl_xor_sync(0xffffffffu, mx1, 2));
        float nrm0 = fmaxf(rm0, mx0), nrm1 = fmaxf(rm1, mx1);
        float al0 = __expf(rm0 - nrm0), al1 = __expf(rm1 - nrm1);
        rm0 = nrm0; rm1 = nrm1;

        float p[8][4];
        float sum0 = 0.f, sum1 = 0.f;
        #pragma unroll
        for (int nt = 0; nt < 8; nt++) {
            p[nt][0] = __expf(sacc[nt][0] - nrm0); sum0 += p[nt][0];
            p[nt][1] = __expf(sacc[nt][1] - nrm0); sum0 += p[nt][1];
            p[nt][2] = __expf(sacc[nt][2] - nrm1); sum1 += p[nt][2];
            p[nt][3] = __expf(sacc[nt][3] - nrm1); sum1 += p[nt][3];
        }
        sum0 += __shfl_xor_sync(0xffffffffu, sum0, 1);
        sum0 += __shfl_xor_sync(0xffffffffu, sum0, 2);
        sum1 += __shfl_xor_sync(0xffffffffu, sum1, 1);
        sum1 += __shfl_xor_sync(0xffffffffu, sum1, 2);
        rs0 = rs0 * al0 + sum0;
        rs1 = rs1 * al1 + sum1;
        #pragma unroll
        for (int nt = 0; nt < 8; nt++) {
            oacc[nt][0] *= al0; oacc[nt][1] *= al0;
            oacc[nt][2] *= al1; oacc[nt][3] *= al1;
        }

        // ---- pack P into A fragments (hi/lo) ----
        uint32_t ph[4][4], pl[4][4];
        #pragma unroll
        for (int ks = 0; ks < 4; ks++) {
            pack_split2(p[2*ks][0],   p[2*ks][1],   ph[ks][0], pl[ks][0]);
            pack_split2(p[2*ks][2],   p[2*ks][3],   ph[ks][1], pl[ks][1]);
            pack_split2(p[2*ks+1][0], p[2*ks+1][1], ph[ks][2], pl[ks][2]);
            pack_split2(p[2*ks+1][2], p[2*ks+1][3], ph[ks][3], pl[ks][3]);
        }

        // ---- O += P V (3-term) ----
        #pragma unroll
        for (int ks = 0; ks < 4; ks++) {
            uint32_t vfh[8][2], vfl[8][2];
            #pragma unroll
            for (int np = 0; np < 4; np++) {
                uint32_t va = (uint32_t)((np * 16 + brow) * AT_RPAD) * 4 + bkof + ks * 32;
                LDMX4(vfh[2*np][0], vfh[2*np][1], vfh[2*np+1][0], vfh[2*np+1][1], Vh_s + va);
                LDMX4(vfl[2*np][0], vfl[2*np][1], vfl[2*np+1][0], vfl[2*np+1][1], Vl_s + va);
            }
            #pragma unroll
            for (int nt = 0; nt < 8; nt++) {
                mma_bf16(oacc[nt][0], oacc[nt][1], oacc[nt][2], oacc[nt][3],
                         ph[ks][0], ph[ks][1], ph[ks][2], ph[ks][3],
                         vfl[nt][0], vfl[nt][1]);
                mma_bf16(oacc[nt][0], oacc[nt][1], oacc[nt][2], oacc[nt][3],
                         pl[ks][0], pl[ks][1], pl[ks][2], pl[ks][3],
                         vfh[nt][0], vfh[nt][1]);
                mma_bf16(oacc[nt][0], oacc[nt][1], oacc[nt][2], oacc[nt][3],
                         ph[ks][0], ph[ks][1], ph[ks][2], ph[ks][3],
                         vfh[nt][0], vfh[nt][1]);
            }
        }
    }

    // ---- epilogue: normalize + split-store ----
    float inv0 = 1.f / rs0, inv1 = 1.f / rs1;
    int trow0 = qt * 64 + wid * 16 + gid;
    #pragma unroll
    for (int nt = 0; nt < 8; nt++) {
        int col = 8 * nt + 2 * tig;
        size_t o0 = ((size_t)(b * T + trow0))     * (NH * HD) + h * HD + col;
        size_t o1 = ((size_t)(b * T + trow0 + 8)) * (NH * HD) + h * HD + col;
        split_store2(Oh, Ol, o0, oacc[nt][0] * inv0, oacc[nt][1] * inv0);
        split_store2(Oh, Ol, o1, oacc[nt][2] * inv1, oacc[nt][3] * inv1);
    }
}

// ---------------- SwiGLU elementwise with split output ----------------
__global__ void silu_mul_split_kernel(const float* __restrict__ g,
                                      const float* __restrict__ u,
                                      bf16* __restrict__ oh, bf16* __restrict__ ol) {
    size_t i = (size_t)blockIdx.x * blockDim.x + threadIdx.x;
    float4 gv = ((const float4*)g)[i];
    float4 uv = ((const float4*)u)[i];
    float rx = gv.x / (1.f + __expf(-gv.x)) * uv.x;
    float ry = gv.y / (1.f + __expf(-gv.y)) * uv.y;
    float rz = gv.z / (1.f + __expf(-gv.z)) * uv.z;
    float rw = gv.w / (1.f + __expf(-gv.w)) * uv.w;
    split_store4(oh, ol, i * 4, rx, ry, rz, rw);
}

// ---------------- launch ----------------
extern "C" void kernel_launch(void* const* d_in, const int* in_sizes, int n_in,
                              void* d_out, int out_size) {
    const float* hs   = (const float*)d_in[0];
    const float* cosp = (const float*)d_in[1];
    const float* sinp = (const float*)d_in[2];
    const int*   pos  = (const int*)  d_in[3];
    const float* n1w  = (const float*)d_in[5];
    const float* wq   = (const float*)d_in[6];
    const float* wk   = (const float*)d_in[7];
    const float* wv   = (const float*)d_in[8];
    const float* wo   = (const float*)d_in[9];
    const float* n2w  = (const float*)d_in[10];
    const float* wg   = (const float*)d_in[11];
    const float* wu   = (const float*)d_in[12];
    const float* wd   = (const float*)d_in[13];

    float *q, *k, *v, *h2, *gg, *uu;
    cudaGetSymbolAddress((void**)&q,  g_q);
    cudaGetSymbolAddress((void**)&k,  g_k);
    cudaGetSymbolAddress((void**)&v,  g_v);
    cudaGetSymbolAddress((void**)&h2, g_h2);
    cudaGetSymbolAddress((void**)&gg, g_gg);
    cudaGetSymbolAddress((void**)&uu, g_uu);

    bf16 *wqh,*wql,*wkh,*wkl,*wvh,*wvl,*woh,*wol,*wgh,*wgl,*wuh,*wul,*wdh,*wdl;
    bf16 *xnh,*xnl,*ath,*atl,*xn2h,*xn2l,*gh,*gl;
    bf16 *qh,*ql,*kh,*kl,*vth,*vtl;
    cudaGetSymbolAddress((void**)&wqh, s_wq_h);  cudaGetSymbolAddress((void**)&wql, s_wq_l);
    cudaGetSymbolAddress((void**)&wkh, s_wk_h);  cudaGetSymbolAddress((void**)&wkl, s_wk_l);
    cudaGetSymbolAddress((void**)&wvh, s_wv_h);  cudaGetSymbolAddress((void**)&wvl, s_wv_l);
    cudaGetSymbolAddress((void**)&woh, s_wo_h);  cudaGetSymbolAddress((void**)&wol, s_wo_l);
    cudaGetSymbolAddress((void**)&wgh, s_wg_h);  cudaGetSymbolAddress((void**)&wgl, s_wg_l);
    cudaGetSymbolAddress((void**)&wuh, s_wu_h);  cudaGetSymbolAddress((void**)&wul, s_wu_l);
    cudaGetSymbolAddress((void**)&wdh, s_wd_h);  cudaGetSymbolAddress((void**)&wdl, s_wd_l);
    cudaGetSymbolAddress((void**)&xnh, s_xn_h);  cudaGetSymbolAddress((void**)&xnl, s_xn_l);
    cudaGetSymbolAddress((void**)&ath, s_at_h);  cudaGetSymbolAddress((void**)&atl, s_at_l);
    cudaGetSymbolAddress((void**)&xn2h, s_xn2_h);cudaGetSymbolAddress((void**)&xn2l, s_xn2_l);
    cudaGetSymbolAddress((void**)&gh,  s_g_h);   cudaGetSymbolAddress((void**)&gl,  s_g_l);
    cudaGetSymbolAddress((void**)&qh,  s_q_h);   cudaGetSymbolAddress((void**)&ql,  s_q_l);
    cudaGetSymbolAddress((void**)&kh,  s_k_h);   cudaGetSymbolAddress((void**)&kl,  s_k_l);
    cudaGetSymbolAddress((void**)&vth, s_vt_h);  cudaGetSymbolAddress((void**)&vtl, s_vt_l);

    float* out_x = (float*)d_out;
    float* out_k = out_x + (size_t)M * H;
    float* out_v = out_k + (size_t)B * NKV * T * HD;

    cudaFuncSetAttribute(gemm_mma_kernel,
                         cudaFuncAttributeMaxDynamicSharedMemorySize, GEMM_DSMEM);
    cudaFuncSetAttribute(gemm_qkv_kernel,
                         cudaFuncAttributeMaxDynamicSharedMemorySize, GEMM_DSMEM);
    cudaFuncSetAttribute(gemm_gu_kernel,
                         cudaFuncAttributeMaxDynamicSharedMemorySize, GEMM_DSMEM);
    cudaFuncSetAttribute(attn_kernel,
                         cudaFuncAttributeMaxDynamicSharedMemorySize, ATTN_DSMEM);

    // 0. split weights
    split_kernel<<<(NH*HD*H/4 + 255)/256, 256>>>(wq, wqh, wql, NH*HD*H/4);
    split_kernel<<<(NKV*HD*H/4 + 255)/256, 256>>>(wk, wkh, wkl, NKV*HD*H/4);
    split_kernel<<<(NKV*HD*H/4 + 255)/256, 256>>>(wv, wvh, wvl, NKV*HD*H/4);
    split_kernel<<<(H*NH*HD/4 + 255)/256, 256>>>(wo, woh, wol, H*NH*HD/4);
    split_kernel<<<(IM*H/4 + 255)/256, 256>>>(wg, wgh, wgl, IM*H/4);
    split_kernel<<<(IM*H/4 + 255)/256, 256>>>(wu, wuh, wul, IM*H/4);
    split_kernel<<<(H*IM/4 + 255)/256, 256>>>(wd, wdh, wdl, H*IM/4);

    // 1. RMSNorm 1
    rmsnorm_split_kernel<<<M, 256>>>(hs, n1w, xnh, xnl);
    // 2. fused Q/K/V projections
    gemm_qkv_kernel<<<dim3(24, M / 64), 256, GEMM_DSMEM>>>(xnh, xnl, q, k, v);
    // 3. RoPE + KV-cache writeout + bf16 splits (q,k head-major; v transposed)
    rope_q_kernel <<<(B * T * NH  * (HD / 2)) / 256, 256>>>(q, cosp, sinp, pos, qh, ql);
    rope_kv_kernel<<<(B * T * NKV * (HD / 2)) / 256, 256>>>(k, v, cosp, sinp, pos,
                                                            out_k, out_v, kh, kl, vth, vtl);
    // 4. Attention (tensor-core, 3xBF16)
    attn_kernel<<<dim3(T / 64, NH, B), 128, ATTN_DSMEM>>>(qh, ql, kh, kl, vth, vtl, ath, atl);
    // 5. O-projection + residual
    gemm_mma_kernel<<<dim3(H / 128, M / 64), 256, GEMM_DSMEM>>>(ath, atl, woh, wol,
                                                                hs, h2, H, NH * HD);
    // 6. RMSNorm 2
    rmsnorm_split_kernel<<<M, 256>>>(h2, n2w, xn2h, xn2l);
    // 7. fused MLP gate/up
    gemm_gu_kernel<<<dim3(128, M / 64), 256, GEMM_DSMEM>>>(xn2h, xn2l, gg, uu);
    // 8. SwiGLU
    silu_mul_split_kernel<<<((size_t)M * IM / 4) / 256, 256>>>(gg, uu, gh, gl);
    // 9. Down projection + residual -> x output
    gemm_mma_kernel<<<dim3(H / 128, M / 64), 256, GEMM_DSMEM>>>(gh, gl, wdh, wdl,
                                                                h2, out_x, H, IM);
}